// round 1
// baseline (speedup 1.0000x reference)
#include <cuda_runtime.h>
#include <cstdint>
#include <cstddef>

// Problem constants
#define BJ   69632           // 4096*17 rows
#define NB   4096
#define NJ   17
#define ND   512
#define NH   8
#define NDK  64

// ---------------- device scratch (allocation-free rule: __device__ globals) ----
__device__ float g_qkv[(size_t)BJ * 1536];   // fused Q|K|V, row = (b*17+j), col = sel*512 + h*64 + e
__device__ float g_o  [(size_t)BJ * 512];    // attention output (head-concat)
__device__ float g_tmp[(size_t)BJ * 512];    // o @ Wo + bo
__device__ float g_x  [(size_t)BJ * 512];    // LN1 output
__device__ float g_h  [(size_t)BJ * 1024];   // h0 | h1
__device__ float g_Wqkv[512 * 1536];
__device__ float g_bqkv[1536];
__device__ float g_Wg[512 * 1024];
__device__ float g_A[NJ * NJ];

// ---------------- weight packing -----------------------------------------------
__global__ void pack_qkv_w(const float* __restrict__ Wq, const float* __restrict__ Wk,
                           const float* __restrict__ Wv, const float* __restrict__ bq,
                           const float* __restrict__ bk, const float* __restrict__ bv) {
    int idx = blockIdx.x * blockDim.x + threadIdx.x;
    if (idx >= 512 * 1536) return;
    int d = idx / 1536, c = idx % 1536;
    int sel = c / 512, cc = c % 512;
    int h = cc / 64, e = cc % 64;
    const float* W = (sel == 0) ? Wq : (sel == 1) ? Wk : Wv;   // [H, D, DK]
    g_Wqkv[idx] = W[((size_t)h * 512 + d) * 64 + e];
    if (d == 0) {
        const float* bb = (sel == 0) ? bq : (sel == 1) ? bk : bv; // [H, DK] flat = cc
        g_bqkv[c] = bb[cc];
    }
}

__global__ void pack_wg(const float* __restrict__ Wgcn) { // [2, 512, 512]
    int idx = blockIdx.x * blockDim.x + threadIdx.x;
    if (idx >= 512 * 1024) return;
    int d = idx / 1024, c = idx % 1024;
    g_Wg[idx] = (c < 512) ? Wgcn[(size_t)d * 512 + c]
                          : Wgcn[(size_t)512 * 512 + (size_t)d * 512 + (c - 512)];
}

// ---------------- adjacency softmax (tiny, one block) ---------------------------
__global__ void build_A(const int* __restrict__ rows, const int* __restrict__ cols,
                        const float* __restrict__ e, int nnz) {
    __shared__ float lg[NJ][NJ];
    int tid = threadIdx.x;
    if (tid < NJ * NJ) lg[tid / NJ][tid % NJ] = -9e15f;
    __syncthreads();
    if (tid < nnz) lg[rows[tid]][cols[tid]] = e[tid];
    __syncthreads();
    if (tid < NJ) {
        float m = -9e15f;
        #pragma unroll
        for (int k = 0; k < NJ; k++) m = fmaxf(m, lg[tid][k]);
        float ex[NJ]; float s = 0.f;
        #pragma unroll
        for (int k = 0; k < NJ; k++) { ex[k] = __expf(lg[tid][k] - m); s += ex[k]; }
        float inv = 1.0f / s;
        #pragma unroll
        for (int k = 0; k < NJ; k++) g_A[tid * NJ + k] = ex[k] * inv;
    }
}

// ---------------- SGEMM: C[M,N] = A[M,512..] @ B[K,N] (+bias) -------------------
// BM=BN=128, BK=16, 256 threads, 8x8 per thread. All dims divide evenly.
__global__ __launch_bounds__(256) void sgemm_bias(
        const float* __restrict__ A, const float* __restrict__ B,
        const float* __restrict__ bias, float* __restrict__ C,
        int N, int K) {
    __shared__ float As[16][128];
    __shared__ float Bs[16][128];
    const int tid = threadIdx.x;
    const int tm = tid >> 4;      // 0..15
    const int tn = tid & 15;      // 0..15
    const float* Ab = A + (size_t)blockIdx.y * 128 * K;
    const float* Bb = B + (size_t)blockIdx.x * 128;

    float acc[8][8];
    #pragma unroll
    for (int i = 0; i < 8; i++)
        #pragma unroll
        for (int j = 0; j < 8; j++) acc[i][j] = 0.f;

    for (int k0 = 0; k0 < K; k0 += 16) {
        // A tile 128x16 (512 float4), transpose into As[k][m]
        #pragma unroll
        for (int l = 0; l < 2; l++) {
            int id = tid + l * 256;
            int r = id >> 2, c4 = (id & 3) << 2;
            float4 v = *(const float4*)(Ab + (size_t)r * K + k0 + c4);
            As[c4 + 0][r] = v.x; As[c4 + 1][r] = v.y;
            As[c4 + 2][r] = v.z; As[c4 + 3][r] = v.w;
        }
        // B tile 16x128 (512 float4)
        #pragma unroll
        for (int l = 0; l < 2; l++) {
            int id = tid + l * 256;
            int r = id >> 5, c4 = (id & 31) << 2;
            *(float4*)&Bs[r][c4] = *(const float4*)(Bb + (size_t)(k0 + r) * N + c4);
        }
        __syncthreads();
        #pragma unroll
        for (int kk = 0; kk < 16; kk++) {
            float a[8], bb[8];
            #pragma unroll
            for (int i = 0; i < 8; i++) a[i]  = As[kk][tm * 8 + i];
            #pragma unroll
            for (int j = 0; j < 8; j++) bb[j] = Bs[kk][tn * 8 + j];
            #pragma unroll
            for (int i = 0; i < 8; i++)
                #pragma unroll
                for (int j = 0; j < 8; j++)
                    acc[i][j] = fmaf(a[i], bb[j], acc[i][j]);
        }
        __syncthreads();
    }
    #pragma unroll
    for (int i = 0; i < 8; i++) {
        size_t row = (size_t)blockIdx.y * 128 + tm * 8 + i;
        float* Crow = C + row * N + (size_t)blockIdx.x * 128 + tn * 8;
        const float* brow = bias ? bias + (size_t)blockIdx.x * 128 + tn * 8 : nullptr;
        #pragma unroll
        for (int j = 0; j < 8; j += 4) {
            float4 v;
            v.x = acc[i][j]; v.y = acc[i][j + 1]; v.z = acc[i][j + 2]; v.w = acc[i][j + 3];
            if (brow) { v.x += brow[j]; v.y += brow[j + 1]; v.z += brow[j + 2]; v.w += brow[j + 3]; }
            *(float4*)(Crow + j) = v;
        }
    }
}

// ---------------- attention: one block per (b,h), warp per query row ------------
__global__ __launch_bounds__(544) void attn_kernel(const float* __restrict__ qkv,
                                                   float* __restrict__ o) {
    int b = blockIdx.x;
    int h = blockIdx.y;
    __shared__ float qs[NJ][64];
    __shared__ float ks[NJ][65];   // pad: lanes read column-wise
    __shared__ float vs[NJ][64];

    int tid = threadIdx.y * 32 + threadIdx.x;
    for (int i = tid; i < NJ * 64; i += 544) {
        int j = i >> 6, e = i & 63;
        const float* base = qkv + ((size_t)(b * NJ + j)) * 1536;
        qs[j][e] = base[h * 64 + e];
        ks[j][e] = base[512 + h * 64 + e];
        vs[j][e] = base[1024 + h * 64 + e];
    }
    __syncthreads();

    int j = threadIdx.y;       // query row 0..16
    int lane = threadIdx.x;
    float s = -1e30f;
    if (lane < NJ) {
        float acc = 0.f;
        #pragma unroll
        for (int e = 0; e < 64; e++) acc = fmaf(qs[j][e], ks[lane][e], acc);
        s = acc * 0.125f;      // / sqrt(64)
    }
    float m = s;
    #pragma unroll
    for (int off = 16; off; off >>= 1) m = fmaxf(m, __shfl_xor_sync(0xffffffffu, m, off));
    float p = (lane < NJ) ? __expf(s - m) : 0.f;
    float sum = p;
    #pragma unroll
    for (int off = 16; off; off >>= 1) sum += __shfl_xor_sync(0xffffffffu, sum, off);
    p *= (1.0f / sum);

    float o0 = 0.f, o1 = 0.f;
    #pragma unroll
    for (int k = 0; k < NJ; k++) {
        float pk = __shfl_sync(0xffffffffu, p, k);
        o0 = fmaf(pk, vs[k][lane], o0);
        o1 = fmaf(pk, vs[k][lane + 32], o1);
    }
    float* orow = o + ((size_t)(b * NJ + j)) * 512 + h * 64;
    orow[lane] = o0;
    orow[lane + 32] = o1;
}

// ---------------- LN1: out = LN(a + r) * g + be ---------------------------------
__global__ __launch_bounds__(256) void add_ln(const float* __restrict__ a,
                                              const float* __restrict__ r,
                                              const float* __restrict__ g,
                                              const float* __restrict__ be,
                                              float* __restrict__ out) {
    int row = blockIdx.x * 8 + threadIdx.y;
    int lane = threadIdx.x;
    const float* ar = a + (size_t)row * 512;
    const float* rr = r + (size_t)row * 512;
    float v[16], s = 0.f, ss = 0.f;
    #pragma unroll
    for (int t = 0; t < 16; t++) {
        int d = lane + (t << 5);
        v[t] = ar[d] + rr[d];
        s += v[t]; ss = fmaf(v[t], v[t], ss);
    }
    #pragma unroll
    for (int off = 16; off; off >>= 1) {
        s  += __shfl_xor_sync(0xffffffffu, s,  off);
        ss += __shfl_xor_sync(0xffffffffu, ss, off);
    }
    float mean = s * (1.0f / 512.0f);
    float var  = ss * (1.0f / 512.0f) - mean * mean;
    float inv  = rsqrtf(var + 1e-5f);
    float* orow = out + (size_t)row * 512;
    #pragma unroll
    for (int t = 0; t < 16; t++) {
        int d = lane + (t << 5);
        orow[d] = (v[t] - mean) * inv * g[d] + be[d];
    }
}

// ---------------- GCN mix (A*I)h0 + (A*(1-I))h1 + bias, residual, LN2 -----------
__global__ __launch_bounds__(544) void gcn_ln2(const float* __restrict__ x,
                                               const float* __restrict__ b_gcn,
                                               const float* __restrict__ g2,
                                               const float* __restrict__ be2,
                                               float* __restrict__ out) {
    int b = blockIdx.x;
    __shared__ float h1s[NJ][512];
    __shared__ float Aoff[NJ][NJ];
    __shared__ float Ad[NJ];
    int tid = threadIdx.y * 32 + threadIdx.x;
    for (int i = tid; i < NJ * 512; i += 544) {
        int k = i >> 9, d = i & 511;
        h1s[k][d] = g_h[((size_t)(b * NJ + k)) * 1024 + 512 + d];
    }
    if (tid < NJ * NJ) {
        int j = tid / NJ, k = tid % NJ;
        float a = g_A[tid];
        Aoff[j][k] = (j == k) ? 0.f : a;
        if (j == k) Ad[j] = a;
    }
    __syncthreads();

    int j = threadIdx.y, lane = threadIdx.x;
    size_t row = (size_t)b * NJ + j;
    const float* h0r = &g_h[row * 1024];
    const float* xr  = x + row * 512;
    float y[16], s = 0.f, ss = 0.f;
    #pragma unroll
    for (int t = 0; t < 16; t++) {
        int d = lane + (t << 5);
        float acc = Ad[j] * h0r[d];
        #pragma unroll
        for (int k = 0; k < NJ; k++) acc = fmaf(Aoff[j][k], h1s[k][d], acc);
        acc += b_gcn[d] + xr[d];
        y[t] = acc; s += acc; ss = fmaf(acc, acc, ss);
    }
    #pragma unroll
    for (int off = 16; off; off >>= 1) {
        s  += __shfl_xor_sync(0xffffffffu, s,  off);
        ss += __shfl_xor_sync(0xffffffffu, ss, off);
    }
    float mean = s * (1.0f / 512.0f);
    float var  = ss * (1.0f / 512.0f) - mean * mean;
    float inv  = rsqrtf(var + 1e-5f);
    float* orow = out + row * 512;
    #pragma unroll
    for (int t = 0; t < 16; t++) {
        int d = lane + (t << 5);
        orow[d] = (y[t] - mean) * inv * g2[d] + be2[d];
    }
}

// ---------------- host launcher --------------------------------------------------
extern "C" void kernel_launch(void* const* d_in, const int* in_sizes, int n_in,
                              void* d_out, int out_size) {
    const float* src   = (const float*)d_in[0];
    const float* Wq    = (const float*)d_in[1];
    const float* bq    = (const float*)d_in[2];
    const float* Wk    = (const float*)d_in[3];
    const float* bk    = (const float*)d_in[4];
    const float* Wv    = (const float*)d_in[5];
    const float* bv    = (const float*)d_in[6];
    const float* Wo    = (const float*)d_in[7];
    const float* bo    = (const float*)d_in[8];
    const float* ln1_g = (const float*)d_in[9];
    const float* ln1_b = (const float*)d_in[10];
    const float* Wgcn  = (const float*)d_in[11];
    const float* egcn  = (const float*)d_in[12];
    const float* bgcn  = (const float*)d_in[13];
    const float* ln2_g = (const float*)d_in[14];
    const float* ln2_b = (const float*)d_in[15];
    const int*   mrows = (const int*)d_in[16];
    const int*   mcols = (const int*)d_in[17];
    int nnz = in_sizes[16];
    float* out = (float*)d_out;

    float *p_qkv, *p_o, *p_tmp, *p_x, *p_h, *p_Wqkv, *p_bqkv, *p_Wg;
    cudaGetSymbolAddress((void**)&p_qkv,  g_qkv);
    cudaGetSymbolAddress((void**)&p_o,    g_o);
    cudaGetSymbolAddress((void**)&p_tmp,  g_tmp);
    cudaGetSymbolAddress((void**)&p_x,    g_x);
    cudaGetSymbolAddress((void**)&p_h,    g_h);
    cudaGetSymbolAddress((void**)&p_Wqkv, g_Wqkv);
    cudaGetSymbolAddress((void**)&p_bqkv, g_bqkv);
    cudaGetSymbolAddress((void**)&p_Wg,   g_Wg);

    // weight packing + adjacency softmax
    pack_qkv_w<<<(512 * 1536 + 255) / 256, 256>>>(Wq, Wk, Wv, bq, bk, bv);
    pack_wg<<<(512 * 1024 + 255) / 256, 256>>>(Wgcn);
    build_A<<<1, 512>>>(mrows, mcols, egcn, nnz);

    // fused QKV GEMM: [BJ,512] @ [512,1536]
    sgemm_bias<<<dim3(1536 / 128, BJ / 128), 256>>>(src, p_Wqkv, p_bqkv, p_qkv, 1536, 512);

    // attention
    attn_kernel<<<dim3(NB, NH), dim3(32, NJ)>>>(p_qkv, p_o);

    // output projection
    sgemm_bias<<<dim3(512 / 128, BJ / 128), 256>>>(p_o, Wo, bo, p_tmp, 512, 512);

    // LN1: x = LN(src + attn_out)
    add_ln<<<BJ / 8, dim3(32, 8)>>>(p_tmp, src, ln1_g, ln1_b, p_x);

    // GCN GEMMs: h0|h1 = x @ [W0|W1]
    sgemm_bias<<<dim3(1024 / 128, BJ / 128), 256>>>(p_x, p_Wg, nullptr, p_h, 1024, 512);

    // GCN mix + bias + residual + LN2 -> out
    gcn_ln2<<<NB, dim3(32, NJ)>>>(p_x, bgcn, ln2_g, ln2_b, out);
}

// round 3
// speedup vs baseline: 2.4836x; 2.4836x over previous
#include <cuda_runtime.h>
#include <cstdint>
#include <cstddef>

// Problem constants
#define BJ   69632           // 4096*17 rows
#define NB   4096
#define NJ   17
#define ND   512
#define NH   8
#define NDK  64

// ---------------- device scratch ------------------------------------------------
__device__ float g_qkv[(size_t)BJ * 1536];   // fused Q|K|V
__device__ float g_o  [(size_t)BJ * 512];    // attention output (head-concat)
__device__ float g_tmp[(size_t)BJ * 512];    // o @ Wo + bo
__device__ float g_x  [(size_t)BJ * 512];    // LN1 output
__device__ float g_h  [(size_t)BJ * 1024];   // h0 | h1
__device__ float g_Wqkv[1536 * 512];         // transposed [N][K]
__device__ float g_bqkv[1536];
__device__ float g_Wo_t[512 * 512];          // transposed [N][K]
__device__ float g_Wg[1024 * 512];           // transposed [N][K]
__device__ float g_A[NJ * NJ];

// ---------------- helpers -------------------------------------------------------
__device__ __forceinline__ uint32_t smem_u32(const void* p) {
    uint32_t a;
    asm("{ .reg .u64 t; cvta.to.shared.u64 t, %1; cvt.u32.u64 %0, t; }" : "=r"(a) : "l"(p));
    return a;
}
__device__ __forceinline__ uint32_t to_tf32(float x) {
    uint32_t u;
    asm("cvt.rna.tf32.f32 %0, %1;" : "=r"(u) : "f"(x));
    return u;
}
__device__ __forceinline__ void cp16(uint32_t saddr, const void* gptr) {
    asm volatile("cp.async.cg.shared.global [%0], [%1], 16;" :: "r"(saddr), "l"(gptr));
}
__device__ __forceinline__ void cp_commit() { asm volatile("cp.async.commit_group;" ::: "memory"); }
__device__ __forceinline__ void cp_wait1()  { asm volatile("cp.async.wait_group 1;" ::: "memory"); }
__device__ __forceinline__ void cp_wait0()  { asm volatile("cp.async.wait_group 0;" ::: "memory"); }

__device__ __forceinline__ void mma_tf32(float& d0, float& d1, float& d2, float& d3,
                                         uint32_t a0, uint32_t a1, uint32_t a2, uint32_t a3,
                                         uint32_t b0, uint32_t b1) {
    asm volatile(
        "mma.sync.aligned.m16n8k8.row.col.f32.tf32.tf32.f32 "
        "{%0,%1,%2,%3}, {%4,%5,%6,%7}, {%8,%9}, {%0,%1,%2,%3};"
        : "+f"(d0), "+f"(d1), "+f"(d2), "+f"(d3)
        : "r"(a0), "r"(a1), "r"(a2), "r"(a3), "r"(b0), "r"(b1));
}

// ================= tf32 mma.sync GEMM: C[M,N] = A[M,512] @ Bt[N,512]^T (+bias) ===
// Tile: BM=128, BN=128, BK=32, 256 threads (8 warps, 2x4), warp tile 64x32.
// SMEM: As[m][k] and Bs[n][k], padded stride 36 floats -> conflict-free frag loads.
#define SLD  36
#define BUFB (128 * SLD * 4)              // bytes per As or Bs buffer: 18432
#define GEMM_SMEM_BYTES (4 * BUFB)        // 2 stages x (A+B) = 73728

__global__ __launch_bounds__(256) void tc_gemm(const float* __restrict__ A,
                                               const float* __restrict__ Bt,
                                               const float* __restrict__ bias,
                                               float* __restrict__ C, int N) {
    extern __shared__ float smem[];
    const uint32_t sb = smem_u32(smem);
    const int tid  = threadIdx.x;
    const int lane = tid & 31;
    const int wid  = tid >> 5;
    const int warp_m = (wid & 1) * 64;    // 2 warp-rows of 64
    const int warp_n = (wid >> 1) * 32;   // 4 warp-cols of 32
    const int r = lane >> 2;              // 0..7
    const int c = lane & 3;               // 0..3

    const float* Abase = A  + (size_t)blockIdx.y * 128 * 512;
    const float* Bbase = Bt + (size_t)blockIdx.x * 128 * 512;

    // cp.async source/dst indexing: 4 segments of 16B per matrix per thread
    const int seg_row[4] = { (tid + 0) >> 3, (tid + 256) >> 3, (tid + 512) >> 3, (tid + 768) >> 3 };
    const int seg_off[4] = { (tid & 7) * 4, (tid & 7) * 4, (tid & 7) * 4, (tid & 7) * 4 };

    auto issue = [&](int t, int buf) {
        const float* Ab = Abase + t * 32;
        const float* Bb = Bbase + t * 32;
        uint32_t sA = sb + buf * 2 * BUFB;
        uint32_t sB = sA + BUFB;
        #pragma unroll
        for (int l = 0; l < 4; ++l) {
            int row = seg_row[l], off = seg_off[l];
            uint32_t so = (uint32_t)(row * SLD + off) * 4u;
            cp16(sA + so, Ab + (size_t)row * 512 + off);
            cp16(sB + so, Bb + (size_t)row * 512 + off);
        }
        cp_commit();
    };

    float acc[4][4][4];
    #pragma unroll
    for (int i = 0; i < 4; ++i)
        #pragma unroll
        for (int j = 0; j < 4; ++j)
            #pragma unroll
            for (int q = 0; q < 4; ++q) acc[i][j][q] = 0.f;

    issue(0, 0);
    issue(1, 1);

    #pragma unroll 1
    for (int t = 0; t < 16; ++t) {
        const int buf = t & 1;
        if (t == 15) cp_wait0(); else cp_wait1();
        __syncthreads();

        const float* As = smem + buf * 2 * (BUFB / 4);
        const float* Bs = As + (BUFB / 4);
        const float* aB = As + (warp_m + r) * SLD + c;
        const float* bB = Bs + (warp_n + r) * SLD + c;

        #pragma unroll
        for (int k8 = 0; k8 < 4; ++k8) {
            const int k0 = k8 * 8;
            uint32_t a[4][4], b[4][2];
            #pragma unroll
            for (int i = 0; i < 4; ++i) {
                const float* p = aB + i * 16 * SLD + k0;
                a[i][0] = to_tf32(p[0]);
                a[i][1] = to_tf32(p[8 * SLD]);
                a[i][2] = to_tf32(p[4]);
                a[i][3] = to_tf32(p[8 * SLD + 4]);
            }
            #pragma unroll
            for (int j = 0; j < 4; ++j) {
                const float* p = bB + j * 8 * SLD + k0;
                b[j][0] = to_tf32(p[0]);
                b[j][1] = to_tf32(p[4]);
            }
            #pragma unroll
            for (int i = 0; i < 4; ++i)
                #pragma unroll
                for (int j = 0; j < 4; ++j)
                    mma_tf32(acc[i][j][0], acc[i][j][1], acc[i][j][2], acc[i][j][3],
                             a[i][0], a[i][1], a[i][2], a[i][3], b[j][0], b[j][1]);
        }
        __syncthreads();
        if (t + 2 < 16) issue(t + 2, buf);
    }

    // epilogue
    const size_t rowBase = (size_t)blockIdx.y * 128 + warp_m + r;
    const int colBase = blockIdx.x * 128 + warp_n + 2 * c;
    #pragma unroll
    for (int i = 0; i < 4; ++i) {
        #pragma unroll
        for (int j = 0; j < 4; ++j) {
            size_t row = rowBase + i * 16;
            int col = colBase + j * 8;
            float b0 = 0.f, b1 = 0.f;
            if (bias) { b0 = bias[col]; b1 = bias[col + 1]; }
            float2 v0 = { acc[i][j][0] + b0, acc[i][j][1] + b1 };
            float2 v1 = { acc[i][j][2] + b0, acc[i][j][3] + b1 };
            *(float2*)(C + row * (size_t)N + col)       = v0;
            *(float2*)(C + (row + 8) * (size_t)N + col) = v1;
        }
    }
}

// ---------------- weight packing (transpose to [N][K]) --------------------------
__global__ void pack_qkv_w(const float* __restrict__ Wq, const float* __restrict__ Wk,
                           const float* __restrict__ Wv, const float* __restrict__ bq,
                           const float* __restrict__ bk, const float* __restrict__ bv) {
    int idx = blockIdx.x * blockDim.x + threadIdx.x;
    if (idx >= 512 * 1536) return;
    int d = idx / 1536, cc2 = idx % 1536;
    int sel = cc2 / 512, cc = cc2 % 512;
    int h = cc / 64, e = cc % 64;
    const float* W = (sel == 0) ? Wq : (sel == 1) ? Wk : Wv;   // [H, D, DK]
    g_Wqkv[(size_t)cc2 * 512 + d] = W[((size_t)h * 512 + d) * 64 + e];
    if (d == 0) {
        const float* bb = (sel == 0) ? bq : (sel == 1) ? bk : bv;
        g_bqkv[cc2] = bb[cc];
    }
}

__global__ void pack_wo(const float* __restrict__ Wo) {  // [512,512] -> [N][K]
    int idx = blockIdx.x * blockDim.x + threadIdx.x;
    if (idx >= 512 * 512) return;
    int n = idx / 512, k = idx % 512;
    g_Wo_t[idx] = Wo[(size_t)k * 512 + n];
}

__global__ void pack_wg(const float* __restrict__ Wgcn) { // [2, 512, 512] -> [1024][512]
    int idx = blockIdx.x * blockDim.x + threadIdx.x;
    if (idx >= 1024 * 512) return;
    int n = idx / 512, k = idx % 512;
    int i = n / 512, cc = n % 512;
    g_Wg[idx] = Wgcn[(size_t)i * 512 * 512 + (size_t)k * 512 + cc];
}

// ---------------- adjacency softmax ---------------------------------------------
__global__ void build_A(const int* __restrict__ rows, const int* __restrict__ cols,
                        const float* __restrict__ e, int nnz) {
    __shared__ float lg[NJ][NJ];
    int tid = threadIdx.x;
    if (tid < NJ * NJ) lg[tid / NJ][tid % NJ] = -9e15f;
    __syncthreads();
    if (tid < nnz) lg[rows[tid]][cols[tid]] = e[tid];
    __syncthreads();
    if (tid < NJ) {
        float m = -9e15f;
        #pragma unroll
        for (int k = 0; k < NJ; k++) m = fmaxf(m, lg[tid][k]);
        float ex[NJ]; float s = 0.f;
        #pragma unroll
        for (int k = 0; k < NJ; k++) { ex[k] = __expf(lg[tid][k] - m); s += ex[k]; }
        float inv = 1.0f / s;
        #pragma unroll
        for (int k = 0; k < NJ; k++) g_A[tid * NJ + k] = ex[k] * inv;
    }
}

// ---------------- attention: one block per (b,h), warp per query row ------------
__global__ __launch_bounds__(544) void attn_kernel(const float* __restrict__ qkv,
                                                   float* __restrict__ o) {
    int b = blockIdx.x;
    int h = blockIdx.y;
    __shared__ float qs[NJ][64];
    __shared__ float ks[NJ][65];
    __shared__ float vs[NJ][64];

    int tid = threadIdx.y * 32 + threadIdx.x;
    for (int i = tid; i < NJ * 64; i += 544) {
        int j = i >> 6, e = i & 63;
        const float* base = qkv + ((size_t)(b * NJ + j)) * 1536;
        qs[j][e] = base[h * 64 + e];
        ks[j][e] = base[512 + h * 64 + e];
        vs[j][e] = base[1024 + h * 64 + e];
    }
    __syncthreads();

    int j = threadIdx.y;
    int lane = threadIdx.x;
    float s = -1e30f;
    if (lane < NJ) {
        float acc = 0.f;
        #pragma unroll
        for (int e = 0; e < 64; e++) acc = fmaf(qs[j][e], ks[lane][e], acc);
        s = acc * 0.125f;
    }
    float m = s;
    #pragma unroll
    for (int off = 16; off; off >>= 1) m = fmaxf(m, __shfl_xor_sync(0xffffffffu, m, off));
    float p = (lane < NJ) ? __expf(s - m) : 0.f;
    float sum = p;
    #pragma unroll
    for (int off = 16; off; off >>= 1) sum += __shfl_xor_sync(0xffffffffu, sum, off);
    p *= (1.0f / sum);

    float o0 = 0.f, o1 = 0.f;
    #pragma unroll
    for (int k = 0; k < NJ; k++) {
        float pk = __shfl_sync(0xffffffffu, p, k);
        o0 = fmaf(pk, vs[k][lane], o0);
        o1 = fmaf(pk, vs[k][lane + 32], o1);
    }
    float* orow = o + ((size_t)(b * NJ + j)) * 512 + h * 64;
    orow[lane] = o0;
    orow[lane + 32] = o1;
}

// ---------------- LN1: out = LN(a + r) * g + be ---------------------------------
__global__ __launch_bounds__(256) void add_ln(const float* __restrict__ a,
                                              const float* __restrict__ r,
                                              const float* __restrict__ g,
                                              const float* __restrict__ be,
                                              float* __restrict__ out) {
    int row = blockIdx.x * 8 + threadIdx.y;
    int lane = threadIdx.x;
    const float* ar = a + (size_t)row * 512;
    const float* rr = r + (size_t)row * 512;
    float v[16], s = 0.f, ss = 0.f;
    #pragma unroll
    for (int t = 0; t < 16; t++) {
        int d = lane + (t << 5);
        v[t] = ar[d] + rr[d];
        s += v[t]; ss = fmaf(v[t], v[t], ss);
    }
    #pragma unroll
    for (int off = 16; off; off >>= 1) {
        s  += __shfl_xor_sync(0xffffffffu, s,  off);
        ss += __shfl_xor_sync(0xffffffffu, ss, off);
    }
    float mean = s * (1.0f / 512.0f);
    float var  = ss * (1.0f / 512.0f) - mean * mean;
    float inv  = rsqrtf(var + 1e-5f);
    float* orow = out + (size_t)row * 512;
    #pragma unroll
    for (int t = 0; t < 16; t++) {
        int d = lane + (t << 5);
        orow[d] = (v[t] - mean) * inv * g[d] + be[d];
    }
}

// ---------------- GCN mix (A*I)h0 + (A*(1-I))h1 + bias, residual, LN2 -----------
__global__ __launch_bounds__(544) void gcn_ln2(const float* __restrict__ x,
                                               const float* __restrict__ b_gcn,
                                               const float* __restrict__ g2,
                                               const float* __restrict__ be2,
                                               float* __restrict__ out) {
    int b = blockIdx.x;
    __shared__ float h1s[NJ][512];
    __shared__ float Aoff[NJ][NJ];
    __shared__ float Ad[NJ];
    int tid = threadIdx.y * 32 + threadIdx.x;
    for (int i = tid; i < NJ * 512; i += 544) {
        int k = i >> 9, d = i & 511;
        h1s[k][d] = g_h[((size_t)(b * NJ + k)) * 1024 + 512 + d];
    }
    if (tid < NJ * NJ) {
        int j = tid / NJ, k = tid % NJ;
        float a = g_A[tid];
        Aoff[j][k] = (j == k) ? 0.f : a;
        if (j == k) Ad[j] = a;
    }
    __syncthreads();

    int j = threadIdx.y, lane = threadIdx.x;
    size_t row = (size_t)b * NJ + j;
    const float* h0r = &g_h[row * 1024];
    const float* xr  = x + row * 512;
    float y[16], s = 0.f, ss = 0.f;
    #pragma unroll
    for (int t = 0; t < 16; t++) {
        int d = lane + (t << 5);
        float acc = Ad[j] * h0r[d];
        #pragma unroll
        for (int k = 0; k < NJ; k++) acc = fmaf(Aoff[j][k], h1s[k][d], acc);
        acc += b_gcn[d] + xr[d];
        y[t] = acc; s += acc; ss = fmaf(acc, acc, ss);
    }
    #pragma unroll
    for (int off = 16; off; off >>= 1) {
        s  += __shfl_xor_sync(0xffffffffu, s,  off);
        ss += __shfl_xor_sync(0xffffffffu, ss, off);
    }
    float mean = s * (1.0f / 512.0f);
    float var  = ss * (1.0f / 512.0f) - mean * mean;
    float inv  = rsqrtf(var + 1e-5f);
    float* orow = out + row * 512;
    #pragma unroll
    for (int t = 0; t < 16; t++) {
        int d = lane + (t << 5);
        orow[d] = (y[t] - mean) * inv * g2[d] + be2[d];
    }
}

// ---------------- host launcher --------------------------------------------------
extern "C" void kernel_launch(void* const* d_in, const int* in_sizes, int n_in,
                              void* d_out, int out_size) {
    const float* src   = (const float*)d_in[0];
    const float* Wq    = (const float*)d_in[1];
    const float* bq    = (const float*)d_in[2];
    const float* Wk    = (const float*)d_in[3];
    const float* bk    = (const float*)d_in[4];
    const float* Wv    = (const float*)d_in[5];
    const float* bv    = (const float*)d_in[6];
    const float* Wo    = (const float*)d_in[7];
    const float* bo    = (const float*)d_in[8];
    const float* ln1_g = (const float*)d_in[9];
    const float* ln1_b = (const float*)d_in[10];
    const float* Wgcn  = (const float*)d_in[11];
    const float* egcn  = (const float*)d_in[12];
    const float* bgcn  = (const float*)d_in[13];
    const float* ln2_g = (const float*)d_in[14];
    const float* ln2_b = (const float*)d_in[15];
    const int*   mrows = (const int*)d_in[16];
    const int*   mcols = (const int*)d_in[17];
    int nnz = in_sizes[16];
    float* out = (float*)d_out;

    float *p_qkv, *p_o, *p_tmp, *p_x, *p_h, *p_Wqkv, *p_bqkv, *p_Wot, *p_Wg;
    cudaGetSymbolAddress((void**)&p_qkv,  g_qkv);
    cudaGetSymbolAddress((void**)&p_o,    g_o);
    cudaGetSymbolAddress((void**)&p_tmp,  g_tmp);
    cudaGetSymbolAddress((void**)&p_x,    g_x);
    cudaGetSymbolAddress((void**)&p_h,    g_h);
    cudaGetSymbolAddress((void**)&p_Wqkv, g_Wqkv);
    cudaGetSymbolAddress((void**)&p_bqkv, g_bqkv);
    cudaGetSymbolAddress((void**)&p_Wot,  g_Wo_t);
    cudaGetSymbolAddress((void**)&p_Wg,   g_Wg);

    cudaFuncSetAttribute(tc_gemm, cudaFuncAttributeMaxDynamicSharedMemorySize, GEMM_SMEM_BYTES);

    // weight packing + adjacency softmax
    pack_qkv_w<<<(512 * 1536 + 255) / 256, 256>>>(Wq, Wk, Wv, bq, bk, bv);
    pack_wo<<<(512 * 512 + 255) / 256, 256>>>(Wo);
    pack_wg<<<(1024 * 512 + 255) / 256, 256>>>(Wgcn);
    build_A<<<1, 512>>>(mrows, mcols, egcn, nnz);

    // fused QKV GEMM: [BJ,512] @ [512,1536]
    tc_gemm<<<dim3(1536 / 128, BJ / 128), 256, GEMM_SMEM_BYTES>>>(src, p_Wqkv, p_bqkv, p_qkv, 1536);

    // attention
    attn_kernel<<<dim3(NB, NH), dim3(32, NJ)>>>(p_qkv, p_o);

    // output projection
    tc_gemm<<<dim3(512 / 128, BJ / 128), 256, GEMM_SMEM_BYTES>>>(p_o, p_Wot, bo, p_tmp, 512);

    // LN1: x = LN(src + attn_out)
    add_ln<<<BJ / 8, dim3(32, 8)>>>(p_tmp, src, ln1_g, ln1_b, p_x);

    // GCN GEMMs: h0|h1 = x @ [W0|W1]
    tc_gemm<<<dim3(1024 / 128, BJ / 128), 256, GEMM_SMEM_BYTES>>>(p_x, p_Wg, nullptr, p_h, 1024);

    // GCN mix + bias + residual + LN2 -> out
    gcn_ln2<<<NB, dim3(32, NJ)>>>(p_x, bgcn, ln2_g, ln2_b, out);
}

// round 4
// speedup vs baseline: 3.7982x; 1.5293x over previous
#include <cuda_runtime.h>
#include <cuda_fp16.h>
#include <cstdint>
#include <cstddef>

// Problem constants
#define BJ   69632           // 4096*17 rows
#define NB   4096
#define NJ   17
#define ND   512
#define NH   8
#define NDK  64

// ---------------- device scratch ------------------------------------------------
__device__ __half g_src_h[(size_t)BJ * 512];   // src as half
__device__ __half g_qkv  [(size_t)BJ * 1536];  // fused Q|K|V (half)
__device__ __half g_o    [(size_t)BJ * 512];   // attention output (half)
__device__ float  g_tmp  [(size_t)BJ * 512];   // o @ Wo + bo (fp32)
__device__ float  g_x    [(size_t)BJ * 512];   // LN1 output (fp32, residual)
__device__ __half g_x_h  [(size_t)BJ * 512];   // LN1 output (half, GEMM operand)
__device__ float  g_h    [(size_t)BJ * 1024];  // h0 | h1 (fp32)
__device__ __half g_Wqkv[1536 * 512];          // transposed [N][K] half
__device__ float  g_bqkv[1536];
__device__ __half g_Wo_t[512 * 512];           // transposed [N][K] half
__device__ __half g_Wg[1024 * 512];            // transposed [N][K] half
__device__ float  g_A[NJ * NJ];

// ---------------- helpers -------------------------------------------------------
__device__ __forceinline__ uint32_t smem_u32(const void* p) {
    uint32_t a;
    asm("{ .reg .u64 t; cvta.to.shared.u64 t, %1; cvt.u32.u64 %0, t; }" : "=r"(a) : "l"(p));
    return a;
}
__device__ __forceinline__ void cp16(uint32_t saddr, const void* gptr) {
    asm volatile("cp.async.cg.shared.global [%0], [%1], 16;" :: "r"(saddr), "l"(gptr));
}
__device__ __forceinline__ void cp_commit() { asm volatile("cp.async.commit_group;" ::: "memory"); }
__device__ __forceinline__ void cp_wait1()  { asm volatile("cp.async.wait_group 1;" ::: "memory"); }
__device__ __forceinline__ void cp_wait0()  { asm volatile("cp.async.wait_group 0;" ::: "memory"); }

__device__ __forceinline__ void ldsm4(uint32_t* r, uint32_t addr) {
    asm volatile("ldmatrix.sync.aligned.m8n8.x4.shared.b16 {%0,%1,%2,%3}, [%4];"
        : "=r"(r[0]), "=r"(r[1]), "=r"(r[2]), "=r"(r[3]) : "r"(addr));
}
__device__ __forceinline__ void mma_f16(float* d, const uint32_t* a, const uint32_t* b) {
    asm volatile(
        "mma.sync.aligned.m16n8k16.row.col.f32.f16.f16.f32 "
        "{%0,%1,%2,%3}, {%4,%5,%6,%7}, {%8,%9}, {%0,%1,%2,%3};"
        : "+f"(d[0]), "+f"(d[1]), "+f"(d[2]), "+f"(d[3])
        : "r"(a[0]), "r"(a[1]), "r"(a[2]), "r"(a[3]), "r"(b[0]), "r"(b[1]));
}

// ================= fp16 mma.sync GEMM: C[M,N] = A[M,512] @ Bt[N,512]^T (+bias) ==
// Tile: BM=128, BN=256, BK=64 halves, 256 threads (8 warps 2x4), warp tile 64x64.
// SMEM rows of 128B (64 halves), XOR swizzle chunk^(row&7): conflict-free STS+LDSM.
#define STAGE_BYTES 49152     // A: 128*128B=16KB, B: 256*128B=32KB
#define GEMM_SMEM   (3 * STAGE_BYTES)

__global__ __launch_bounds__(256) void tc_gemm(const __half* __restrict__ A,
                                               const __half* __restrict__ Bt,
                                               const float* __restrict__ bias,
                                               void* __restrict__ C, int N,
                                               int out_half) {
    extern __shared__ char smem[];
    const uint32_t sb = smem_u32(smem);
    const int tid  = threadIdx.x;
    const int lane = tid & 31;
    const int wid  = tid >> 5;
    const int warp_m = (wid & 1) * 64;
    const int warp_n = (wid >> 1) * 64;
    const int l7 = lane & 7;
    const int a_row_base = warp_m + l7 + ((lane & 8) ? 8 : 0);
    const int a_cc_add = (lane & 16) ? 1 : 0;
    const int b_row_base = warp_n + l7 + ((lane & 16) ? 8 : 0);
    const int b_cc_add = (lane & 8) ? 1 : 0;

    const __half* Abase = A  + (size_t)blockIdx.y * 128 * 512;
    const __half* Bbase = Bt + (size_t)blockIdx.x * 256 * 512;

    auto issue = [&](int t) {
        const int buf = t % 3;
        const uint32_t sA = sb + buf * STAGE_BYTES;
        const uint32_t sB = sA + 16384;
        const __half* Ab = Abase + t * 64;
        const __half* Bb = Bbase + t * 64;
        #pragma unroll
        for (int ll = 0; ll < 4; ++ll) {
            int id = tid + ll * 256, row = id >> 3, cc = id & 7;
            cp16(sA + row * 128 + ((cc ^ (row & 7)) << 4), Ab + (size_t)row * 512 + cc * 8);
        }
        #pragma unroll
        for (int ll = 0; ll < 8; ++ll) {
            int id = tid + ll * 256, row = id >> 3, cc = id & 7;
            cp16(sB + row * 128 + ((cc ^ (row & 7)) << 4), Bb + (size_t)row * 512 + cc * 8);
        }
        cp_commit();
    };

    float acc[4][8][4];
    #pragma unroll
    for (int i = 0; i < 4; ++i)
        #pragma unroll
        for (int j = 0; j < 8; ++j)
            #pragma unroll
            for (int q = 0; q < 4; ++q) acc[i][j][q] = 0.f;

    issue(0);
    issue(1);

    #pragma unroll 1
    for (int t = 0; t < 8; ++t) {
        if (t < 7) cp_wait1(); else cp_wait0();
        __syncthreads();
        if (t + 2 < 8) issue(t + 2);

        const int buf = t % 3;
        const uint32_t sA = sb + buf * STAGE_BYTES;
        const uint32_t sB = sA + 16384;

        #pragma unroll
        for (int q = 0; q < 4; ++q) {
            const int kc = 2 * q;
            uint32_t af[4][4], bf[4][4];
            #pragma unroll
            for (int i = 0; i < 4; ++i)
                ldsm4(af[i], sA + (uint32_t)(a_row_base + i * 16) * 128 +
                              (uint32_t)(((kc + a_cc_add) ^ l7) << 4));
            #pragma unroll
            for (int j2 = 0; j2 < 4; ++j2)
                ldsm4(bf[j2], sB + (uint32_t)(b_row_base + j2 * 16) * 128 +
                               (uint32_t)(((kc + b_cc_add) ^ l7) << 4));
            #pragma unroll
            for (int i = 0; i < 4; ++i)
                #pragma unroll
                for (int j = 0; j < 8; ++j)
                    mma_f16(acc[i][j], af[i], &bf[j >> 1][(j & 1) * 2]);
        }
        __syncthreads();
    }

    // epilogue
    const size_t rowBase = (size_t)blockIdx.y * 128 + warp_m + (lane >> 2);
    const int colBase = blockIdx.x * 256 + warp_n + (lane & 3) * 2;
    #pragma unroll
    for (int i = 0; i < 4; ++i) {
        #pragma unroll
        for (int j = 0; j < 8; ++j) {
            size_t m0 = rowBase + i * 16;
            int n0 = colBase + j * 8;
            float b0 = 0.f, b1 = 0.f;
            if (bias) { b0 = bias[n0]; b1 = bias[n0 + 1]; }
            float v00 = acc[i][j][0] + b0, v01 = acc[i][j][1] + b1;
            float v10 = acc[i][j][2] + b0, v11 = acc[i][j][3] + b1;
            if (out_half) {
                __half* Ch = (__half*)C;
                *(__half2*)(Ch + m0 * (size_t)N + n0)       = __floats2half2_rn(v00, v01);
                *(__half2*)(Ch + (m0 + 8) * (size_t)N + n0) = __floats2half2_rn(v10, v11);
            } else {
                float* Cf = (float*)C;
                *(float2*)(Cf + m0 * (size_t)N + n0)       = make_float2(v00, v01);
                *(float2*)(Cf + (m0 + 8) * (size_t)N + n0) = make_float2(v10, v11);
            }
        }
    }
}

// ---------------- src -> half ---------------------------------------------------
__global__ void conv_src(const float* __restrict__ src) {
    size_t idx = (size_t)blockIdx.x * blockDim.x + threadIdx.x;
    if (idx >= (size_t)BJ * 256) return;
    float2 v = *(const float2*)(src + idx * 2);
    *(__half2*)(g_src_h + idx * 2) = __floats2half2_rn(v.x, v.y);
}

// ---------------- weight packing (transpose to [N][K], half) --------------------
__global__ void pack_qkv_w(const float* __restrict__ Wq, const float* __restrict__ Wk,
                           const float* __restrict__ Wv, const float* __restrict__ bq,
                           const float* __restrict__ bk, const float* __restrict__ bv) {
    int idx = blockIdx.x * blockDim.x + threadIdx.x;
    if (idx >= 512 * 1536) return;
    int d = idx / 1536, cc2 = idx % 1536;
    int sel = cc2 / 512, cc = cc2 % 512;
    int h = cc / 64, e = cc % 64;
    const float* W = (sel == 0) ? Wq : (sel == 1) ? Wk : Wv;   // [H, D, DK]
    g_Wqkv[(size_t)cc2 * 512 + d] = __float2half_rn(W[((size_t)h * 512 + d) * 64 + e]);
    if (d == 0) {
        const float* bb = (sel == 0) ? bq : (sel == 1) ? bk : bv;
        g_bqkv[cc2] = bb[cc];
    }
}

__global__ void pack_wo(const float* __restrict__ Wo) {  // [512,512] -> [N][K]
    int idx = blockIdx.x * blockDim.x + threadIdx.x;
    if (idx >= 512 * 512) return;
    int n = idx / 512, k = idx % 512;
    g_Wo_t[idx] = __float2half_rn(Wo[(size_t)k * 512 + n]);
}

__global__ void pack_wg(const float* __restrict__ Wgcn) { // [2, 512, 512] -> [1024][512]
    int idx = blockIdx.x * blockDim.x + threadIdx.x;
    if (idx >= 1024 * 512) return;
    int n = idx / 512, k = idx % 512;
    int i = n / 512, cc = n % 512;
    g_Wg[idx] = __float2half_rn(Wgcn[(size_t)i * 512 * 512 + (size_t)k * 512 + cc]);
}

// ---------------- adjacency softmax ---------------------------------------------
__global__ void build_A(const int* __restrict__ rows, const int* __restrict__ cols,
                        const float* __restrict__ e, int nnz) {
    __shared__ float lg[NJ][NJ];
    int tid = threadIdx.x;
    if (tid < NJ * NJ) lg[tid / NJ][tid % NJ] = -9e15f;
    __syncthreads();
    if (tid < nnz) lg[rows[tid]][cols[tid]] = e[tid];
    __syncthreads();
    if (tid < NJ) {
        float m = -9e15f;
        #pragma unroll
        for (int k = 0; k < NJ; k++) m = fmaxf(m, lg[tid][k]);
        float ex[NJ]; float s = 0.f;
        #pragma unroll
        for (int k = 0; k < NJ; k++) { ex[k] = __expf(lg[tid][k] - m); s += ex[k]; }
        float inv = 1.0f / s;
        #pragma unroll
        for (int k = 0; k < NJ; k++) g_A[tid * NJ + k] = ex[k] * inv;
    }
}

// ---------------- attention: one block per (b,h), warp per query row ------------
__global__ __launch_bounds__(544) void attn_kernel(const __half* __restrict__ qkv,
                                                   __half* __restrict__ o) {
    int b = blockIdx.x;
    int h = blockIdx.y;
    __shared__ float qs[NJ][64];
    __shared__ float ks[NJ][65];
    __shared__ float vs[NJ][64];

    int tid = threadIdx.y * 32 + threadIdx.x;
    for (int i = tid; i < NJ * 32; i += 544) {
        int j = i >> 5, e2 = i & 31;
        const __half* base = qkv + ((size_t)(b * NJ + j)) * 1536;
        float2 q2 = __half22float2(*(const __half2*)(base + h * 64 + e2 * 2));
        float2 k2 = __half22float2(*(const __half2*)(base + 512 + h * 64 + e2 * 2));
        float2 v2 = __half22float2(*(const __half2*)(base + 1024 + h * 64 + e2 * 2));
        qs[j][e2 * 2] = q2.x; qs[j][e2 * 2 + 1] = q2.y;
        ks[j][e2 * 2] = k2.x; ks[j][e2 * 2 + 1] = k2.y;
        vs[j][e2 * 2] = v2.x; vs[j][e2 * 2 + 1] = v2.y;
    }
    __syncthreads();

    int j = threadIdx.y;
    int lane = threadIdx.x;
    float s = -1e30f;
    if (lane < NJ) {
        float acc = 0.f;
        #pragma unroll
        for (int e = 0; e < 64; e++) acc = fmaf(qs[j][e], ks[lane][e], acc);
        s = acc * 0.125f;
    }
    float m = s;
    #pragma unroll
    for (int off = 16; off; off >>= 1) m = fmaxf(m, __shfl_xor_sync(0xffffffffu, m, off));
    float p = (lane < NJ) ? __expf(s - m) : 0.f;
    float sum = p;
    #pragma unroll
    for (int off = 16; off; off >>= 1) sum += __shfl_xor_sync(0xffffffffu, sum, off);
    p *= (1.0f / sum);

    float o0 = 0.f, o1 = 0.f;
    #pragma unroll
    for (int k = 0; k < NJ; k++) {
        float pk = __shfl_sync(0xffffffffu, p, k);
        o0 = fmaf(pk, vs[k][lane], o0);
        o1 = fmaf(pk, vs[k][lane + 32], o1);
    }
    __half* orow = o + ((size_t)(b * NJ + j)) * 512 + h * 64;
    orow[lane] = __float2half_rn(o0);
    orow[lane + 32] = __float2half_rn(o1);
}

// ---------------- LN1: x = LN(a + r), writes fp32 + half ------------------------
__global__ __launch_bounds__(256) void add_ln(const float* __restrict__ a,
                                              const float* __restrict__ r,
                                              const float* __restrict__ g,
                                              const float* __restrict__ be,
                                              float* __restrict__ out,
                                              __half* __restrict__ outh) {
    int row = blockIdx.x * 8 + threadIdx.y;
    int lane = threadIdx.x;
    const float* ar = a + (size_t)row * 512;
    const float* rr = r + (size_t)row * 512;
    float v[16], s = 0.f, ss = 0.f;
    #pragma unroll
    for (int t = 0; t < 16; t++) {
        int d = lane + (t << 5);
        v[t] = ar[d] + rr[d];
        s += v[t]; ss = fmaf(v[t], v[t], ss);
    }
    #pragma unroll
    for (int off = 16; off; off >>= 1) {
        s  += __shfl_xor_sync(0xffffffffu, s,  off);
        ss += __shfl_xor_sync(0xffffffffu, ss, off);
    }
    float mean = s * (1.0f / 512.0f);
    float var  = ss * (1.0f / 512.0f) - mean * mean;
    float inv  = rsqrtf(var + 1e-5f);
    float* orow = out + (size_t)row * 512;
    __half* hrow = outh + (size_t)row * 512;
    #pragma unroll
    for (int t = 0; t < 16; t++) {
        int d = lane + (t << 5);
        float y = (v[t] - mean) * inv * g[d] + be[d];
        orow[d] = y;
        hrow[d] = __float2half_rn(y);
    }
}

// ---------------- GCN mix (A*I)h0 + (A*(1-I))h1 + bias, residual, LN2 -----------
__global__ __launch_bounds__(544) void gcn_ln2(const float* __restrict__ x,
                                               const float* __restrict__ b_gcn,
                                               const float* __restrict__ g2,
                                               const float* __restrict__ be2,
                                               float* __restrict__ out) {
    int b = blockIdx.x;
    __shared__ float h1s[NJ][512];
    __shared__ float Aoff[NJ][NJ];
    __shared__ float Ad[NJ];
    int tid = threadIdx.y * 32 + threadIdx.x;
    for (int i = tid; i < NJ * 512; i += 544) {
        int k = i >> 9, d = i & 511;
        h1s[k][d] = g_h[((size_t)(b * NJ + k)) * 1024 + 512 + d];
    }
    if (tid < NJ * NJ) {
        int j = tid / NJ, k = tid % NJ;
        float a = g_A[tid];
        Aoff[j][k] = (j == k) ? 0.f : a;
        if (j == k) Ad[j] = a;
    }
    __syncthreads();

    int j = threadIdx.y, lane = threadIdx.x;
    size_t row = (size_t)b * NJ + j;
    const float* h0r = &g_h[row * 1024];
    const float* xr  = x + row * 512;
    float y[16], s = 0.f, ss = 0.f;
    #pragma unroll
    for (int t = 0; t < 16; t++) {
        int d = lane + (t << 5);
        float acc = Ad[j] * h0r[d];
        #pragma unroll
        for (int k = 0; k < NJ; k++) acc = fmaf(Aoff[j][k], h1s[k][d], acc);
        acc += b_gcn[d] + xr[d];
        y[t] = acc; s += acc; ss = fmaf(acc, acc, ss);
    }
    #pragma unroll
    for (int off = 16; off; off >>= 1) {
        s  += __shfl_xor_sync(0xffffffffu, s,  off);
        ss += __shfl_xor_sync(0xffffffffu, ss, off);
    }
    float mean = s * (1.0f / 512.0f);
    float var  = ss * (1.0f / 512.0f) - mean * mean;
    float inv  = rsqrtf(var + 1e-5f);
    float* orow = out + row * 512;
    #pragma unroll
    for (int t = 0; t < 16; t++) {
        int d = lane + (t << 5);
        orow[d] = (y[t] - mean) * inv * g2[d] + be2[d];
    }
}

// ---------------- host launcher --------------------------------------------------
extern "C" void kernel_launch(void* const* d_in, const int* in_sizes, int n_in,
                              void* d_out, int out_size) {
    const float* src   = (const float*)d_in[0];
    const float* Wq    = (const float*)d_in[1];
    const float* bq    = (const float*)d_in[2];
    const float* Wk    = (const float*)d_in[3];
    const float* bk    = (const float*)d_in[4];
    const float* Wv    = (const float*)d_in[5];
    const float* bv    = (const float*)d_in[6];
    const float* Wo    = (const float*)d_in[7];
    const float* bo    = (const float*)d_in[8];
    const float* ln1_g = (const float*)d_in[9];
    const float* ln1_b = (const float*)d_in[10];
    const float* Wgcn  = (const float*)d_in[11];
    const float* egcn  = (const float*)d_in[12];
    const float* bgcn  = (const float*)d_in[13];
    const float* ln2_g = (const float*)d_in[14];
    const float* ln2_b = (const float*)d_in[15];
    const int*   mrows = (const int*)d_in[16];
    const int*   mcols = (const int*)d_in[17];
    int nnz = in_sizes[16];
    float* out = (float*)d_out;

    __half *p_srch, *p_qkv, *p_o, *p_xh, *p_Wqkv, *p_Wot, *p_Wg;
    float *p_tmp, *p_x, *p_h, *p_bqkv;
    cudaGetSymbolAddress((void**)&p_srch, g_src_h);
    cudaGetSymbolAddress((void**)&p_qkv,  g_qkv);
    cudaGetSymbolAddress((void**)&p_o,    g_o);
    cudaGetSymbolAddress((void**)&p_tmp,  g_tmp);
    cudaGetSymbolAddress((void**)&p_x,    g_x);
    cudaGetSymbolAddress((void**)&p_xh,   g_x_h);
    cudaGetSymbolAddress((void**)&p_h,    g_h);
    cudaGetSymbolAddress((void**)&p_Wqkv, g_Wqkv);
    cudaGetSymbolAddress((void**)&p_bqkv, g_bqkv);
    cudaGetSymbolAddress((void**)&p_Wot,  g_Wo_t);
    cudaGetSymbolAddress((void**)&p_Wg,   g_Wg);

    cudaFuncSetAttribute(tc_gemm, cudaFuncAttributeMaxDynamicSharedMemorySize, GEMM_SMEM);

    // conversions, weight packing, adjacency softmax
    conv_src<<<(BJ * 256 + 255) / 256, 256>>>(src);
    pack_qkv_w<<<(512 * 1536 + 255) / 256, 256>>>(Wq, Wk, Wv, bq, bk, bv);
    pack_wo<<<(512 * 512 + 255) / 256, 256>>>(Wo);
    pack_wg<<<(1024 * 512 + 255) / 256, 256>>>(Wgcn);
    build_A<<<1, 512>>>(mrows, mcols, egcn, nnz);

    // fused QKV GEMM: [BJ,512] @ [512,1536] -> half
    tc_gemm<<<dim3(1536 / 256, BJ / 128), 256, GEMM_SMEM>>>(p_srch, p_Wqkv, p_bqkv, p_qkv, 1536, 1);

    // attention
    attn_kernel<<<dim3(NB, NH), dim3(32, NJ)>>>(p_qkv, p_o);

    // output projection -> fp32 tmp
    tc_gemm<<<dim3(512 / 256, BJ / 128), 256, GEMM_SMEM>>>(p_o, p_Wot, bo, p_tmp, 512, 0);

    // LN1: x = LN(src + attn_out)
    add_ln<<<BJ / 8, dim3(32, 8)>>>(p_tmp, src, ln1_g, ln1_b, p_x, p_xh);

    // GCN GEMMs: h0|h1 = x @ [W0|W1] -> fp32
    tc_gemm<<<dim3(1024 / 256, BJ / 128), 256, GEMM_SMEM>>>(p_xh, p_Wg, nullptr, p_h, 1024, 0);

    // GCN mix + bias + residual + LN2 -> out
    gcn_ln2<<<NB, dim3(32, NJ)>>>(p_x, bgcn, ln2_g, ln2_b, out);
}

// round 5
// speedup vs baseline: 3.9630x; 1.0434x over previous
#include <cuda_runtime.h>
#include <cuda_fp16.h>
#include <cstdint>
#include <cstddef>

// Problem constants
#define BJ   69632           // 4096*17 rows
#define NB   4096
#define NJ   17
#define ND   512
#define NH   8
#define NDK  64

// ---------------- device scratch ------------------------------------------------
__device__ __half g_src_h[(size_t)BJ * 512];   // src as half
__device__ __half g_qkv  [(size_t)BJ * 1536];  // fused Q|K|V (half)
__device__ __half g_o    [(size_t)BJ * 512];   // attention output (half)
__device__ __half g_x_h  [(size_t)BJ * 512];   // LN1 output (half)
__device__ __half g_h_h  [(size_t)BJ * 1024];  // h0 | h1 (half)
__device__ __half g_Wqkv[1536 * 512];          // transposed [N][K] half
__device__ float  g_bqkv[1536];
__device__ __half g_Wo_t[512 * 512];           // transposed [N][K] half
__device__ __half g_Wg[1024 * 512];            // transposed [N][K] half
__device__ float  g_A[NJ * NJ];

// ---------------- helpers -------------------------------------------------------
__device__ __forceinline__ uint32_t smem_u32(const void* p) {
    uint32_t a;
    asm("{ .reg .u64 t; cvta.to.shared.u64 t, %1; cvt.u32.u64 %0, t; }" : "=r"(a) : "l"(p));
    return a;
}
__device__ __forceinline__ void cp16(uint32_t saddr, const void* gptr) {
    asm volatile("cp.async.cg.shared.global [%0], [%1], 16;" :: "r"(saddr), "l"(gptr));
}
__device__ __forceinline__ void cp_commit() { asm volatile("cp.async.commit_group;" ::: "memory"); }
__device__ __forceinline__ void cp_wait1()  { asm volatile("cp.async.wait_group 1;" ::: "memory"); }
__device__ __forceinline__ void cp_wait0()  { asm volatile("cp.async.wait_group 0;" ::: "memory"); }

__device__ __forceinline__ void ldsm4(uint32_t* r, uint32_t addr) {
    asm volatile("ldmatrix.sync.aligned.m8n8.x4.shared.b16 {%0,%1,%2,%3}, [%4];"
        : "=r"(r[0]), "=r"(r[1]), "=r"(r[2]), "=r"(r[3]) : "r"(addr));
}
__device__ __forceinline__ void mma_f16(float* d, const uint32_t* a, const uint32_t* b) {
    asm volatile(
        "mma.sync.aligned.m16n8k16.row.col.f32.f16.f16.f32 "
        "{%0,%1,%2,%3}, {%4,%5,%6,%7}, {%8,%9}, {%0,%1,%2,%3};"
        : "+f"(d[0]), "+f"(d[1]), "+f"(d[2]), "+f"(d[3])
        : "r"(a[0]), "r"(a[1]), "r"(a[2]), "r"(a[3]), "r"(b[0]), "r"(b[1]));
}

// ================= fp16 mma.sync GEMM: C[M,N] = A[M,512] @ Bt[N,512]^T (+bias) ==
// Tile: BM=128, BN=256, BK=64 halves, 256 threads (8 warps 2x4), warp tile 64x64.
#define STAGE_BYTES 49152     // A: 128*128B=16KB, B: 256*128B=32KB
#define GEMM_SMEM   (3 * STAGE_BYTES)

__global__ __launch_bounds__(256) void tc_gemm(const __half* __restrict__ A,
                                               const __half* __restrict__ Bt,
                                               const float* __restrict__ bias,
                                               void* __restrict__ C, int N,
                                               int out_half) {
    extern __shared__ char smem[];
    const uint32_t sb = smem_u32(smem);
    const int tid  = threadIdx.x;
    const int lane = tid & 31;
    const int wid  = tid >> 5;
    const int warp_m = (wid & 1) * 64;
    const int warp_n = (wid >> 1) * 64;
    const int l7 = lane & 7;
    const int a_row_base = warp_m + l7 + ((lane & 8) ? 8 : 0);
    const int a_cc_add = (lane & 16) ? 1 : 0;
    const int b_row_base = warp_n + l7 + ((lane & 16) ? 8 : 0);
    const int b_cc_add = (lane & 8) ? 1 : 0;

    const __half* Abase = A  + (size_t)blockIdx.y * 128 * 512;
    const __half* Bbase = Bt + (size_t)blockIdx.x * 256 * 512;

    auto issue = [&](int t) {
        const int buf = t % 3;
        const uint32_t sA = sb + buf * STAGE_BYTES;
        const uint32_t sB = sA + 16384;
        const __half* Ab = Abase + t * 64;
        const __half* Bb = Bbase + t * 64;
        #pragma unroll
        for (int ll = 0; ll < 4; ++ll) {
            int id = tid + ll * 256, row = id >> 3, cc = id & 7;
            cp16(sA + row * 128 + ((cc ^ (row & 7)) << 4), Ab + (size_t)row * 512 + cc * 8);
        }
        #pragma unroll
        for (int ll = 0; ll < 8; ++ll) {
            int id = tid + ll * 256, row = id >> 3, cc = id & 7;
            cp16(sB + row * 128 + ((cc ^ (row & 7)) << 4), Bb + (size_t)row * 512 + cc * 8);
        }
        cp_commit();
    };

    float acc[4][8][4];
    #pragma unroll
    for (int i = 0; i < 4; ++i)
        #pragma unroll
        for (int j = 0; j < 8; ++j)
            #pragma unroll
            for (int q = 0; q < 4; ++q) acc[i][j][q] = 0.f;

    issue(0);
    issue(1);

    #pragma unroll 1
    for (int t = 0; t < 8; ++t) {
        if (t < 7) cp_wait1(); else cp_wait0();
        __syncthreads();
        if (t + 2 < 8) issue(t + 2);

        const int buf = t % 3;
        const uint32_t sA = sb + buf * STAGE_BYTES;
        const uint32_t sB = sA + 16384;

        #pragma unroll
        for (int q = 0; q < 4; ++q) {
            const int kc = 2 * q;
            uint32_t af[4][4], bf[4][4];
            #pragma unroll
            for (int i = 0; i < 4; ++i)
                ldsm4(af[i], sA + (uint32_t)(a_row_base + i * 16) * 128 +
                              (uint32_t)(((kc + a_cc_add) ^ l7) << 4));
            #pragma unroll
            for (int j2 = 0; j2 < 4; ++j2)
                ldsm4(bf[j2], sB + (uint32_t)(b_row_base + j2 * 16) * 128 +
                               (uint32_t)(((kc + b_cc_add) ^ l7) << 4));
            #pragma unroll
            for (int i = 0; i < 4; ++i)
                #pragma unroll
                for (int j = 0; j < 8; ++j)
                    mma_f16(acc[i][j], af[i], &bf[j >> 1][(j & 1) * 2]);
        }
        __syncthreads();
    }

    // epilogue
    const size_t rowBase = (size_t)blockIdx.y * 128 + warp_m + (lane >> 2);
    const int colBase = blockIdx.x * 256 + warp_n + (lane & 3) * 2;
    #pragma unroll
    for (int i = 0; i < 4; ++i) {
        #pragma unroll
        for (int j = 0; j < 8; ++j) {
            size_t m0 = rowBase + i * 16;
            int n0 = colBase + j * 8;
            float b0 = 0.f, b1 = 0.f;
            if (bias) { b0 = bias[n0]; b1 = bias[n0 + 1]; }
            float v00 = acc[i][j][0] + b0, v01 = acc[i][j][1] + b1;
            float v10 = acc[i][j][2] + b0, v11 = acc[i][j][3] + b1;
            if (out_half) {
                __half* Ch = (__half*)C;
                *(__half2*)(Ch + m0 * (size_t)N + n0)       = __floats2half2_rn(v00, v01);
                *(__half2*)(Ch + (m0 + 8) * (size_t)N + n0) = __floats2half2_rn(v10, v11);
            } else {
                float* Cf = (float*)C;
                *(float2*)(Cf + m0 * (size_t)N + n0)       = make_float2(v00, v01);
                *(float2*)(Cf + (m0 + 8) * (size_t)N + n0) = make_float2(v10, v11);
            }
        }
    }
}

// ===== fused Wo-GEMM + bias + residual(src) + LayerNorm1 -> x_h (half) ==========
// BM=64, BN=512 (full row), BK=64, 256 threads (8 warps, each 64 rows x 64 cols).
#define LNG_STAGE (8192 + 65536)      // A: 64*128B, B: 512*128B
#define LNG_SMEM  (3 * LNG_STAGE)

__global__ __launch_bounds__(256) void ln_gemm(const __half* __restrict__ A,
                                               const __half* __restrict__ Bt,
                                               const float* __restrict__ bias,
                                               const float* __restrict__ src,
                                               const float* __restrict__ gam,
                                               const float* __restrict__ bet,
                                               __half* __restrict__ outh) {
    extern __shared__ char smem[];
    const uint32_t sb = smem_u32(smem);
    const int tid  = threadIdx.x;
    const int lane = tid & 31;
    const int wid  = tid >> 5;
    const int warp_n = wid * 64;
    const int l7 = lane & 7;
    const int a_row_base = l7 + ((lane & 8) ? 8 : 0);
    const int a_cc_add = (lane & 16) ? 1 : 0;
    const int b_row_base = warp_n + l7 + ((lane & 16) ? 8 : 0);
    const int b_cc_add = (lane & 8) ? 1 : 0;

    const size_t rowBlk = (size_t)blockIdx.x * 64;
    const __half* Abase = A + rowBlk * 512;

    auto issue = [&](int t) {
        const int buf = t % 3;
        const uint32_t sA = sb + buf * LNG_STAGE;
        const uint32_t sB = sA + 8192;
        const __half* Ab = Abase + t * 64;
        const __half* Bb = Bt + t * 64;
        #pragma unroll
        for (int ll = 0; ll < 2; ++ll) {
            int id = tid + ll * 256, row = id >> 3, cc = id & 7;
            cp16(sA + row * 128 + ((cc ^ (row & 7)) << 4), Ab + (size_t)row * 512 + cc * 8);
        }
        #pragma unroll
        for (int ll = 0; ll < 16; ++ll) {
            int id = tid + ll * 256, row = id >> 3, cc = id & 7;
            cp16(sB + row * 128 + ((cc ^ (row & 7)) << 4), Bb + (size_t)row * 512 + cc * 8);
        }
        cp_commit();
    };

    float acc[4][8][4];
    #pragma unroll
    for (int i = 0; i < 4; ++i)
        #pragma unroll
        for (int j = 0; j < 8; ++j)
            #pragma unroll
            for (int q = 0; q < 4; ++q) acc[i][j][q] = 0.f;

    issue(0);
    issue(1);

    #pragma unroll 1
    for (int t = 0; t < 8; ++t) {
        if (t < 7) cp_wait1(); else cp_wait0();
        __syncthreads();
        if (t + 2 < 8) issue(t + 2);

        const int buf = t % 3;
        const uint32_t sA = sb + buf * LNG_STAGE;
        const uint32_t sB = sA + 8192;

        #pragma unroll
        for (int q = 0; q < 4; ++q) {
            const int kc = 2 * q;
            uint32_t af[4][4], bf[4][4];
            #pragma unroll
            for (int i = 0; i < 4; ++i)
                ldsm4(af[i], sA + (uint32_t)(a_row_base + i * 16) * 128 +
                              (uint32_t)(((kc + a_cc_add) ^ l7) << 4));
            #pragma unroll
            for (int j2 = 0; j2 < 4; ++j2)
                ldsm4(bf[j2], sB + (uint32_t)(b_row_base + j2 * 16) * 128 +
                               (uint32_t)(((kc + b_cc_add) ^ l7) << 4));
            #pragma unroll
            for (int i = 0; i < 4; ++i)
                #pragma unroll
                for (int j = 0; j < 8; ++j)
                    mma_f16(acc[i][j], af[i], &bf[j >> 1][(j & 1) * 2]);
        }
        __syncthreads();
    }

    // ---- epilogue: v = acc + bias + src; LN over full row (512 cols) ----
    float2* red  = (float2*)smem;          // [64 rows][8 warps]
    float2* stat = (float2*)(smem + 4096); // [64 rows] (mean, inv)
    const int rq = lane >> 2;              // row offset within 8
    const int cq = (lane & 3) * 2;

    #pragma unroll
    for (int i = 0; i < 4; ++i) {
        #pragma unroll
        for (int h2 = 0; h2 < 2; ++h2) {
            int row_local = rq + i * 16 + h2 * 8;
            size_t grow = (rowBlk + row_local) * 512;
            float s = 0.f, ss = 0.f;
            #pragma unroll
            for (int j = 0; j < 8; ++j) {
                int col = warp_n + cq + j * 8;
                float2 sv = *(const float2*)(src + grow + col);
                float v0 = acc[i][j][h2 * 2 + 0] + bias[col]     + sv.x;
                float v1 = acc[i][j][h2 * 2 + 1] + bias[col + 1] + sv.y;
                acc[i][j][h2 * 2 + 0] = v0;
                acc[i][j][h2 * 2 + 1] = v1;
                s += v0 + v1;
                ss = fmaf(v0, v0, ss); ss = fmaf(v1, v1, ss);
            }
            s  += __shfl_xor_sync(0xffffffffu, s, 1);  s  += __shfl_xor_sync(0xffffffffu, s, 2);
            ss += __shfl_xor_sync(0xffffffffu, ss, 1); ss += __shfl_xor_sync(0xffffffffu, ss, 2);
            if ((lane & 3) == 0) red[row_local * 8 + wid] = make_float2(s, ss);
        }
    }
    __syncthreads();
    if (tid < 64) {
        float s = 0.f, ss = 0.f;
        #pragma unroll
        for (int w = 0; w < 8; ++w) {
            float2 v = red[tid * 8 + w];
            s += v.x; ss += v.y;
        }
        float mean = s * (1.0f / 512.0f);
        float var  = ss * (1.0f / 512.0f) - mean * mean;
        stat[tid] = make_float2(mean, rsqrtf(var + 1e-5f));
    }
    __syncthreads();
    #pragma unroll
    for (int i = 0; i < 4; ++i) {
        #pragma unroll
        for (int h2 = 0; h2 < 2; ++h2) {
            int row_local = rq + i * 16 + h2 * 8;
            float2 st = stat[row_local];
            size_t grow = (rowBlk + row_local) * 512;
            #pragma unroll
            for (int j = 0; j < 8; ++j) {
                int col = warp_n + cq + j * 8;
                float y0 = (acc[i][j][h2 * 2 + 0] - st.x) * st.y * gam[col]     + bet[col];
                float y1 = (acc[i][j][h2 * 2 + 1] - st.x) * st.y * gam[col + 1] + bet[col + 1];
                *(__half2*)(outh + grow + col) = __floats2half2_rn(y0, y1);
            }
        }
    }
}

// ---------------- src -> half ---------------------------------------------------
__global__ void conv_src(const float* __restrict__ src) {
    size_t idx = (size_t)blockIdx.x * blockDim.x + threadIdx.x;
    if (idx >= (size_t)BJ * 256) return;
    float2 v = *(const float2*)(src + idx * 2);
    *(__half2*)(g_src_h + idx * 2) = __floats2half2_rn(v.x, v.y);
}

// ---------------- weight packing (transpose to [N][K], half) --------------------
__global__ void pack_qkv_w(const float* __restrict__ Wq, const float* __restrict__ Wk,
                           const float* __restrict__ Wv, const float* __restrict__ bq,
                           const float* __restrict__ bk, const float* __restrict__ bv) {
    int idx = blockIdx.x * blockDim.x + threadIdx.x;
    if (idx >= 512 * 1536) return;
    int d = idx / 1536, cc2 = idx % 1536;
    int sel = cc2 / 512, cc = cc2 % 512;
    int h = cc / 64, e = cc % 64;
    const float* W = (sel == 0) ? Wq : (sel == 1) ? Wk : Wv;   // [H, D, DK]
    g_Wqkv[(size_t)cc2 * 512 + d] = __float2half_rn(W[((size_t)h * 512 + d) * 64 + e]);
    if (d == 0) {
        const float* bb = (sel == 0) ? bq : (sel == 1) ? bk : bv;
        g_bqkv[cc2] = bb[cc];
    }
}

__global__ void pack_wo(const float* __restrict__ Wo) {  // [512,512] -> [N][K]
    int idx = blockIdx.x * blockDim.x + threadIdx.x;
    if (idx >= 512 * 512) return;
    int n = idx / 512, k = idx % 512;
    g_Wo_t[idx] = __float2half_rn(Wo[(size_t)k * 512 + n]);
}

__global__ void pack_wg(const float* __restrict__ Wgcn) { // [2, 512, 512] -> [1024][512]
    int idx = blockIdx.x * blockDim.x + threadIdx.x;
    if (idx >= 1024 * 512) return;
    int n = idx / 512, k = idx % 512;
    int i = n / 512, cc = n % 512;
    g_Wg[idx] = __float2half_rn(Wgcn[(size_t)i * 512 * 512 + (size_t)k * 512 + cc]);
}

// ---------------- adjacency softmax ---------------------------------------------
__global__ void build_A(const int* __restrict__ rows, const int* __restrict__ cols,
                        const float* __restrict__ e, int nnz) {
    __shared__ float lg[NJ][NJ];
    int tid = threadIdx.x;
    if (tid < NJ * NJ) lg[tid / NJ][tid % NJ] = -9e15f;
    __syncthreads();
    if (tid < nnz) lg[rows[tid]][cols[tid]] = e[tid];
    __syncthreads();
    if (tid < NJ) {
        float m = -9e15f;
        #pragma unroll
        for (int k = 0; k < NJ; k++) m = fmaxf(m, lg[tid][k]);
        float ex[NJ]; float s = 0.f;
        #pragma unroll
        for (int k = 0; k < NJ; k++) { ex[k] = __expf(lg[tid][k] - m); s += ex[k]; }
        float inv = 1.0f / s;
        #pragma unroll
        for (int k = 0; k < NJ; k++) g_A[tid * NJ + k] = ex[k] * inv;
    }
}

// ---------------- attention: one block per (b,h), warp per query row ------------
__global__ __launch_bounds__(544) void attn_kernel(const __half* __restrict__ qkv,
                                                   __half* __restrict__ o) {
    int b = blockIdx.x;
    int h = blockIdx.y;
    __shared__ float qs[NJ][64];
    __shared__ float ks[NJ][65];
    __shared__ float vs[NJ][64];

    int tid = threadIdx.y * 32 + threadIdx.x;
    for (int i = tid; i < NJ * 32; i += 544) {
        int j = i >> 5, e2 = i & 31;
        const __half* base = qkv + ((size_t)(b * NJ + j)) * 1536;
        float2 q2 = __half22float2(*(const __half2*)(base + h * 64 + e2 * 2));
        float2 k2 = __half22float2(*(const __half2*)(base + 512 + h * 64 + e2 * 2));
        float2 v2 = __half22float2(*(const __half2*)(base + 1024 + h * 64 + e2 * 2));
        qs[j][e2 * 2] = q2.x; qs[j][e2 * 2 + 1] = q2.y;
        ks[j][e2 * 2] = k2.x; ks[j][e2 * 2 + 1] = k2.y;
        vs[j][e2 * 2] = v2.x; vs[j][e2 * 2 + 1] = v2.y;
    }
    __syncthreads();

    int j = threadIdx.y;
    int lane = threadIdx.x;
    float s = -1e30f;
    if (lane < NJ) {
        float acc = 0.f;
        #pragma unroll
        for (int e = 0; e < 64; e++) acc = fmaf(qs[j][e], ks[lane][e], acc);
        s = acc * 0.125f;
    }
    float m = s;
    #pragma unroll
    for (int off = 16; off; off >>= 1) m = fmaxf(m, __shfl_xor_sync(0xffffffffu, m, off));
    float p = (lane < NJ) ? __expf(s - m) : 0.f;
    float sum = p;
    #pragma unroll
    for (int off = 16; off; off >>= 1) sum += __shfl_xor_sync(0xffffffffu, sum, off);
    p *= (1.0f / sum);

    float o0 = 0.f, o1 = 0.f;
    #pragma unroll
    for (int k = 0; k < NJ; k++) {
        float pk = __shfl_sync(0xffffffffu, p, k);
        o0 = fmaf(pk, vs[k][lane], o0);
        o1 = fmaf(pk, vs[k][lane + 32], o1);
    }
    __half* orow = o + ((size_t)(b * NJ + j)) * 512 + h * 64;
    orow[lane] = __float2half_rn(o0);
    orow[lane + 32] = __float2half_rn(o1);
}

// ---------------- GCN mix + bias + residual + LN2 -> out (fp32) -----------------
__global__ __launch_bounds__(544) void gcn_ln2(const __half* __restrict__ x,
                                               const float* __restrict__ b_gcn,
                                               const float* __restrict__ g2,
                                               const float* __restrict__ be2,
                                               float* __restrict__ out) {
    int b = blockIdx.x;
    __shared__ float h1s[NJ][512];
    __shared__ float Aoff[NJ][NJ];
    __shared__ float Ad[NJ];
    int tid = threadIdx.y * 32 + threadIdx.x;
    for (int i = tid; i < NJ * 256; i += 544) {
        int k = i >> 8, e2 = i & 255;
        float2 v = __half22float2(*(const __half2*)(g_h_h + ((size_t)(b * NJ + k)) * 1024 + 512 + e2 * 2));
        h1s[k][e2 * 2] = v.x; h1s[k][e2 * 2 + 1] = v.y;
    }
    if (tid < NJ * NJ) {
        int j = tid / NJ, k = tid % NJ;
        float a = g_A[tid];
        Aoff[j][k] = (j == k) ? 0.f : a;
        if (j == k) Ad[j] = a;
    }
    __syncthreads();

    int j = threadIdx.y, lane = threadIdx.x;
    size_t row = (size_t)b * NJ + j;
    const __half* h0r = g_h_h + row * 1024;
    const __half* xr  = x + row * 512;
    float y[16], s = 0.f, ss = 0.f;
    #pragma unroll
    for (int t = 0; t < 16; t++) {
        int d = lane + (t << 5);
        float acc = Ad[j] * __half2float(h0r[d]);
        #pragma unroll
        for (int k = 0; k < NJ; k++) acc = fmaf(Aoff[j][k], h1s[k][d], acc);
        acc += b_gcn[d] + __half2float(xr[d]);
        y[t] = acc; s += acc; ss = fmaf(acc, acc, ss);
    }
    #pragma unroll
    for (int off = 16; off; off >>= 1) {
        s  += __shfl_xor_sync(0xffffffffu, s,  off);
        ss += __shfl_xor_sync(0xffffffffu, ss, off);
    }
    float mean = s * (1.0f / 512.0f);
    float var  = ss * (1.0f / 512.0f) - mean * mean;
    float inv  = rsqrtf(var + 1e-5f);
    float* orow = out + row * 512;
    #pragma unroll
    for (int t = 0; t < 16; t++) {
        int d = lane + (t << 5);
        orow[d] = (y[t] - mean) * inv * g2[d] + be2[d];
    }
}

// ---------------- host launcher --------------------------------------------------
extern "C" void kernel_launch(void* const* d_in, const int* in_sizes, int n_in,
                              void* d_out, int out_size) {
    const float* src   = (const float*)d_in[0];
    const float* Wq    = (const float*)d_in[1];
    const float* bq    = (const float*)d_in[2];
    const float* Wk    = (const float*)d_in[3];
    const float* bk    = (const float*)d_in[4];
    const float* Wv    = (const float*)d_in[5];
    const float* bv    = (const float*)d_in[6];
    const float* Wo    = (const float*)d_in[7];
    const float* bo    = (const float*)d_in[8];
    const float* ln1_g = (const float*)d_in[9];
    const float* ln1_b = (const float*)d_in[10];
    const float* Wgcn  = (const float*)d_in[11];
    const float* egcn  = (const float*)d_in[12];
    const float* bgcn  = (const float*)d_in[13];
    const float* ln2_g = (const float*)d_in[14];
    const float* ln2_b = (const float*)d_in[15];
    const int*   mrows = (const int*)d_in[16];
    const int*   mcols = (const int*)d_in[17];
    int nnz = in_sizes[16];
    float* out = (float*)d_out;

    __half *p_srch, *p_qkv, *p_o, *p_xh, *p_hh, *p_Wqkv, *p_Wot, *p_Wg;
    float *p_bqkv;
    cudaGetSymbolAddress((void**)&p_srch, g_src_h);
    cudaGetSymbolAddress((void**)&p_qkv,  g_qkv);
    cudaGetSymbolAddress((void**)&p_o,    g_o);
    cudaGetSymbolAddress((void**)&p_xh,   g_x_h);
    cudaGetSymbolAddress((void**)&p_hh,   g_h_h);
    cudaGetSymbolAddress((void**)&p_Wqkv, g_Wqkv);
    cudaGetSymbolAddress((void**)&p_bqkv, g_bqkv);
    cudaGetSymbolAddress((void**)&p_Wot,  g_Wo_t);
    cudaGetSymbolAddress((void**)&p_Wg,   g_Wg);

    cudaFuncSetAttribute(tc_gemm, cudaFuncAttributeMaxDynamicSharedMemorySize, GEMM_SMEM);
    cudaFuncSetAttribute(ln_gemm, cudaFuncAttributeMaxDynamicSharedMemorySize, LNG_SMEM);

    // conversions, weight packing, adjacency softmax
    conv_src<<<(BJ * 256 + 255) / 256, 256>>>(src);
    pack_qkv_w<<<(512 * 1536 + 255) / 256, 256>>>(Wq, Wk, Wv, bq, bk, bv);
    pack_wo<<<(512 * 512 + 255) / 256, 256>>>(Wo);
    pack_wg<<<(1024 * 512 + 255) / 256, 256>>>(Wgcn);
    build_A<<<1, 512>>>(mrows, mcols, egcn, nnz);

    // fused QKV GEMM: [BJ,512] @ [512,1536] -> half
    tc_gemm<<<dim3(1536 / 256, BJ / 128), 256, GEMM_SMEM>>>(p_srch, p_Wqkv, p_bqkv, p_qkv, 1536, 1);

    // attention
    attn_kernel<<<dim3(NB, NH), dim3(32, NJ)>>>(p_qkv, p_o);

    // fused: x = LN(src + o @ Wo + bo) -> half
    ln_gemm<<<BJ / 64, 256, LNG_SMEM>>>(p_o, p_Wot, bo, src, ln1_g, ln1_b, p_xh);

    // GCN GEMMs: h0|h1 = x @ [W0|W1] -> half
    tc_gemm<<<dim3(1024 / 256, BJ / 128), 256, GEMM_SMEM>>>(p_xh, p_Wg, nullptr, p_hh, 1024, 1);

    // GCN mix + bias + residual + LN2 -> out
    gcn_ln2<<<NB, dim3(32, NJ)>>>(p_xh, bgcn, ln2_g, ln2_b, out);
}

// round 6
// speedup vs baseline: 4.0639x; 1.0255x over previous
#include <cuda_runtime.h>
#include <cuda_fp16.h>
#include <cstdint>
#include <cstddef>

// Problem constants
#define BJ   69632           // 4096*17 rows
#define NB   4096
#define NJ   17
#define ND   512
#define NH   8
#define NDK  64

// ---------------- device scratch ------------------------------------------------
__device__ __half g_src_h[(size_t)BJ * 512];   // src as half
__device__ __half g_qkv  [(size_t)BJ * 1536];  // fused Q|K|V (half)
__device__ __half g_o    [(size_t)BJ * 512];   // attention output (half)
__device__ __half g_x_h  [(size_t)BJ * 512];   // LN1 output (half)
__device__ __half g_u    [(size_t)BJ * 1024];  // premixed GCN input (half)
__device__ __half g_Wqkv[1536 * 512];          // transposed [N][K] half
__device__ float  g_bqkv[1536];
__device__ __half g_Wo_t[512 * 512];           // transposed [N][K] half
__device__ __half g_Wcat[512 * 1024];          // [N=512][K=1024]: [W0-W1 ; W1]^T half
__device__ float  g_A[NJ * NJ];

// ---------------- helpers -------------------------------------------------------
__device__ __forceinline__ uint32_t smem_u32(const void* p) {
    uint32_t a;
    asm("{ .reg .u64 t; cvta.to.shared.u64 t, %1; cvt.u32.u64 %0, t; }" : "=r"(a) : "l"(p));
    return a;
}
__device__ __forceinline__ void cp16(uint32_t saddr, const void* gptr) {
    asm volatile("cp.async.cg.shared.global [%0], [%1], 16;" :: "r"(saddr), "l"(gptr));
}
__device__ __forceinline__ void cp_commit() { asm volatile("cp.async.commit_group;" ::: "memory"); }
__device__ __forceinline__ void cp_wait1()  { asm volatile("cp.async.wait_group 1;" ::: "memory"); }
__device__ __forceinline__ void cp_wait0()  { asm volatile("cp.async.wait_group 0;" ::: "memory"); }

__device__ __forceinline__ void ldsm4(uint32_t* r, uint32_t addr) {
    asm volatile("ldmatrix.sync.aligned.m8n8.x4.shared.b16 {%0,%1,%2,%3}, [%4];"
        : "=r"(r[0]), "=r"(r[1]), "=r"(r[2]), "=r"(r[3]) : "r"(addr));
}
__device__ __forceinline__ void mma_f16(float* d, const uint32_t* a, const uint32_t* b) {
    asm volatile(
        "mma.sync.aligned.m16n8k16.row.col.f32.f16.f16.f32 "
        "{%0,%1,%2,%3}, {%4,%5,%6,%7}, {%8,%9}, {%0,%1,%2,%3};"
        : "+f"(d[0]), "+f"(d[1]), "+f"(d[2]), "+f"(d[3])
        : "r"(a[0]), "r"(a[1]), "r"(a[2]), "r"(a[3]), "r"(b[0]), "r"(b[1]));
}

// ================= fp16 mma.sync GEMM: C[M,N] = A[M,512] @ Bt[N,512]^T (+bias) ==
// Tile: BM=128, BN=256, BK=64 halves, 256 threads (8 warps 2x4), warp tile 64x64.
#define STAGE_BYTES 49152     // A: 128*128B=16KB, B: 256*128B=32KB
#define GEMM_SMEM   (3 * STAGE_BYTES)

__global__ __launch_bounds__(256) void tc_gemm(const __half* __restrict__ A,
                                               const __half* __restrict__ Bt,
                                               const float* __restrict__ bias,
                                               __half* __restrict__ C, int N) {
    extern __shared__ char smem[];
    const uint32_t sb = smem_u32(smem);
    const int tid  = threadIdx.x;
    const int lane = tid & 31;
    const int wid  = tid >> 5;
    const int warp_m = (wid & 1) * 64;
    const int warp_n = (wid >> 1) * 64;
    const int l7 = lane & 7;
    const int a_row_base = warp_m + l7 + ((lane & 8) ? 8 : 0);
    const int a_cc_add = (lane & 16) ? 1 : 0;
    const int b_row_base = warp_n + l7 + ((lane & 16) ? 8 : 0);
    const int b_cc_add = (lane & 8) ? 1 : 0;

    const __half* Abase = A  + (size_t)blockIdx.y * 128 * 512;
    const __half* Bbase = Bt + (size_t)blockIdx.x * 256 * 512;

    auto issue = [&](int t) {
        const int buf = t % 3;
        const uint32_t sA = sb + buf * STAGE_BYTES;
        const uint32_t sB = sA + 16384;
        const __half* Ab = Abase + t * 64;
        const __half* Bb = Bbase + t * 64;
        #pragma unroll
        for (int ll = 0; ll < 4; ++ll) {
            int id = tid + ll * 256, row = id >> 3, cc = id & 7;
            cp16(sA + row * 128 + ((cc ^ (row & 7)) << 4), Ab + (size_t)row * 512 + cc * 8);
        }
        #pragma unroll
        for (int ll = 0; ll < 8; ++ll) {
            int id = tid + ll * 256, row = id >> 3, cc = id & 7;
            cp16(sB + row * 128 + ((cc ^ (row & 7)) << 4), Bb + (size_t)row * 512 + cc * 8);
        }
        cp_commit();
    };

    float acc[4][8][4];
    #pragma unroll
    for (int i = 0; i < 4; ++i)
        #pragma unroll
        for (int j = 0; j < 8; ++j)
            #pragma unroll
            for (int q = 0; q < 4; ++q) acc[i][j][q] = 0.f;

    issue(0);
    issue(1);

    #pragma unroll 1
    for (int t = 0; t < 8; ++t) {
        if (t < 7) cp_wait1(); else cp_wait0();
        __syncthreads();
        if (t + 2 < 8) issue(t + 2);

        const int buf = t % 3;
        const uint32_t sA = sb + buf * STAGE_BYTES;
        const uint32_t sB = sA + 16384;

        #pragma unroll
        for (int q = 0; q < 4; ++q) {
            const int kc = 2 * q;
            uint32_t af[4][4], bf[4][4];
            #pragma unroll
            for (int i = 0; i < 4; ++i)
                ldsm4(af[i], sA + (uint32_t)(a_row_base + i * 16) * 128 +
                              (uint32_t)(((kc + a_cc_add) ^ l7) << 4));
            #pragma unroll
            for (int j2 = 0; j2 < 4; ++j2)
                ldsm4(bf[j2], sB + (uint32_t)(b_row_base + j2 * 16) * 128 +
                               (uint32_t)(((kc + b_cc_add) ^ l7) << 4));
            #pragma unroll
            for (int i = 0; i < 4; ++i)
                #pragma unroll
                for (int j = 0; j < 8; ++j)
                    mma_f16(acc[i][j], af[i], &bf[j >> 1][(j & 1) * 2]);
        }
    }

    // epilogue (registers only)
    const size_t rowBase = (size_t)blockIdx.y * 128 + warp_m + (lane >> 2);
    const int colBase = blockIdx.x * 256 + warp_n + (lane & 3) * 2;
    #pragma unroll
    for (int i = 0; i < 4; ++i) {
        #pragma unroll
        for (int j = 0; j < 8; ++j) {
            size_t m0 = rowBase + i * 16;
            int n0 = colBase + j * 8;
            float b0 = bias[n0], b1 = bias[n0 + 1];
            *(__half2*)(C + m0 * (size_t)N + n0) =
                __floats2half2_rn(acc[i][j][0] + b0, acc[i][j][1] + b1);
            *(__half2*)(C + (m0 + 8) * (size_t)N + n0) =
                __floats2half2_rn(acc[i][j][2] + b0, acc[i][j][3] + b1);
        }
    }
}

// ===== fused GEMM + bias + residual + LayerNorm (full 512-wide rows) ============
// BM=64, BN=512, BK=64, 256 threads (8 warps, each 64 rows x 64 cols).
// Template: NCHUNK = K/64; RES_HALF: residual tensor dtype; OUT_HALF: output dtype.
#define LNG_STAGE (8192 + 65536)      // A: 64*128B, B: 512*128B
#define LNG_SMEM  (3 * LNG_STAGE)

template<int NCHUNK, bool RES_HALF, bool OUT_HALF>
__global__ __launch_bounds__(256) void ln_gemm_t(const __half* __restrict__ A,
                                                 const __half* __restrict__ Bt,
                                                 const float* __restrict__ bias,
                                                 const void* __restrict__ resid,
                                                 const float* __restrict__ gam,
                                                 const float* __restrict__ bet,
                                                 void* __restrict__ outp) {
    constexpr int K = NCHUNK * 64;
    extern __shared__ char smem[];
    const uint32_t sb = smem_u32(smem);
    const int tid  = threadIdx.x;
    const int lane = tid & 31;
    const int wid  = tid >> 5;
    const int warp_n = wid * 64;
    const int l7 = lane & 7;
    const int a_row_base = l7 + ((lane & 8) ? 8 : 0);
    const int a_cc_add = (lane & 16) ? 1 : 0;
    const int b_row_base = warp_n + l7 + ((lane & 16) ? 8 : 0);
    const int b_cc_add = (lane & 8) ? 1 : 0;

    const size_t rowBlk = (size_t)blockIdx.x * 64;
    const __half* Abase = A + rowBlk * K;

    auto issue = [&](int t) {
        const int buf = t % 3;
        const uint32_t sA = sb + buf * LNG_STAGE;
        const uint32_t sB = sA + 8192;
        const __half* Ab = Abase + t * 64;
        const __half* Bb = Bt + t * 64;
        #pragma unroll
        for (int ll = 0; ll < 2; ++ll) {
            int id = tid + ll * 256, row = id >> 3, cc = id & 7;
            cp16(sA + row * 128 + ((cc ^ (row & 7)) << 4), Ab + (size_t)row * K + cc * 8);
        }
        #pragma unroll
        for (int ll = 0; ll < 16; ++ll) {
            int id = tid + ll * 256, row = id >> 3, cc = id & 7;
            cp16(sB + row * 128 + ((cc ^ (row & 7)) << 4), Bb + (size_t)row * K + cc * 8);
        }
        cp_commit();
    };

    float acc[4][8][4];
    #pragma unroll
    for (int i = 0; i < 4; ++i)
        #pragma unroll
        for (int j = 0; j < 8; ++j)
            #pragma unroll
            for (int q = 0; q < 4; ++q) acc[i][j][q] = 0.f;

    issue(0);
    issue(1);

    #pragma unroll 1
    for (int t = 0; t < NCHUNK; ++t) {
        if (t < NCHUNK - 1) cp_wait1(); else cp_wait0();
        __syncthreads();
        if (t + 2 < NCHUNK) issue(t + 2);

        const int buf = t % 3;
        const uint32_t sA = sb + buf * LNG_STAGE;
        const uint32_t sB = sA + 8192;

        #pragma unroll
        for (int q = 0; q < 4; ++q) {
            const int kc = 2 * q;
            uint32_t af[4][4], bf[4][4];
            #pragma unroll
            for (int i = 0; i < 4; ++i)
                ldsm4(af[i], sA + (uint32_t)(a_row_base + i * 16) * 128 +
                              (uint32_t)(((kc + a_cc_add) ^ l7) << 4));
            #pragma unroll
            for (int j2 = 0; j2 < 4; ++j2)
                ldsm4(bf[j2], sB + (uint32_t)(b_row_base + j2 * 16) * 128 +
                               (uint32_t)(((kc + b_cc_add) ^ l7) << 4));
            #pragma unroll
            for (int i = 0; i < 4; ++i)
                #pragma unroll
                for (int j = 0; j < 8; ++j)
                    mma_f16(acc[i][j], af[i], &bf[j >> 1][(j & 1) * 2]);
        }
    }
    __syncthreads();   // protect smem reuse below

    // ---- epilogue: v = acc + bias + resid; LN over full row (512 cols) ----
    float2* red  = (float2*)smem;          // [64 rows][8 warps]
    float2* stat = (float2*)(smem + 4096); // [64 rows] (mean, inv)
    const int rq = lane >> 2;
    const int cq = (lane & 3) * 2;

    #pragma unroll
    for (int i = 0; i < 4; ++i) {
        #pragma unroll
        for (int h2 = 0; h2 < 2; ++h2) {
            int row_local = rq + i * 16 + h2 * 8;
            size_t grow = (rowBlk + row_local) * 512;
            float s = 0.f, ss = 0.f;
            #pragma unroll
            for (int j = 0; j < 8; ++j) {
                int col = warp_n + cq + j * 8;
                float2 sv;
                if (RES_HALF)
                    sv = __half22float2(*(const __half2*)((const __half*)resid + grow + col));
                else
                    sv = *(const float2*)((const float*)resid + grow + col);
                float v0 = acc[i][j][h2 * 2 + 0] + bias[col]     + sv.x;
                float v1 = acc[i][j][h2 * 2 + 1] + bias[col + 1] + sv.y;
                acc[i][j][h2 * 2 + 0] = v0;
                acc[i][j][h2 * 2 + 1] = v1;
                s += v0 + v1;
                ss = fmaf(v0, v0, ss); ss = fmaf(v1, v1, ss);
            }
            s  += __shfl_xor_sync(0xffffffffu, s, 1);  s  += __shfl_xor_sync(0xffffffffu, s, 2);
            ss += __shfl_xor_sync(0xffffffffu, ss, 1); ss += __shfl_xor_sync(0xffffffffu, ss, 2);
            if ((lane & 3) == 0) red[row_local * 8 + wid] = make_float2(s, ss);
        }
    }
    __syncthreads();
    if (tid < 64) {
        float s = 0.f, ss = 0.f;
        #pragma unroll
        for (int w = 0; w < 8; ++w) {
            float2 v = red[tid * 8 + w];
            s += v.x; ss += v.y;
        }
        float mean = s * (1.0f / 512.0f);
        float var  = ss * (1.0f / 512.0f) - mean * mean;
        stat[tid] = make_float2(mean, rsqrtf(var + 1e-5f));
    }
    __syncthreads();
    #pragma unroll
    for (int i = 0; i < 4; ++i) {
        #pragma unroll
        for (int h2 = 0; h2 < 2; ++h2) {
            int row_local = rq + i * 16 + h2 * 8;
            float2 st = stat[row_local];
            size_t grow = (rowBlk + row_local) * 512;
            #pragma unroll
            for (int j = 0; j < 8; ++j) {
                int col = warp_n + cq + j * 8;
                float y0 = (acc[i][j][h2 * 2 + 0] - st.x) * st.y * gam[col]     + bet[col];
                float y1 = (acc[i][j][h2 * 2 + 1] - st.x) * st.y * gam[col + 1] + bet[col + 1];
                if (OUT_HALF)
                    *(__half2*)((__half*)outp + grow + col) = __floats2half2_rn(y0, y1);
                else
                    *(float2*)((float*)outp + grow + col) = make_float2(y0, y1);
            }
        }
    }
}

// ---------------- src -> half ---------------------------------------------------
__global__ void conv_src(const float* __restrict__ src) {
    size_t idx = (size_t)blockIdx.x * blockDim.x + threadIdx.x;
    if (idx >= (size_t)BJ * 256) return;
    float2 v = *(const float2*)(src + idx * 2);
    *(__half2*)(g_src_h + idx * 2) = __floats2half2_rn(v.x, v.y);
}

// ---------------- weight packing (transpose to [N][K], half) --------------------
__global__ void pack_qkv_w(const float* __restrict__ Wq, const float* __restrict__ Wk,
                           const float* __restrict__ Wv, const float* __restrict__ bq,
                           const float* __restrict__ bk, const float* __restrict__ bv) {
    int idx = blockIdx.x * blockDim.x + threadIdx.x;
    if (idx >= 512 * 1536) return;
    int d = idx / 1536, cc2 = idx % 1536;
    int sel = cc2 / 512, cc = cc2 % 512;
    int h = cc / 64, e = cc % 64;
    const float* W = (sel == 0) ? Wq : (sel == 1) ? Wk : Wv;   // [H, D, DK]
    g_Wqkv[(size_t)cc2 * 512 + d] = __float2half_rn(W[((size_t)h * 512 + d) * 64 + e]);
    if (d == 0) {
        const float* bb = (sel == 0) ? bq : (sel == 1) ? bk : bv;
        g_bqkv[cc2] = bb[cc];
    }
}

__global__ void pack_wo(const float* __restrict__ Wo) {  // [512,512] -> [N][K]
    int idx = blockIdx.x * blockDim.x + threadIdx.x;
    if (idx >= 512 * 512) return;
    int n = idx / 512, k = idx % 512;
    g_Wo_t[idx] = __float2half_rn(Wo[(size_t)k * 512 + n]);
}

// W_cat[n][k]: k<512 -> (W0-W1)[k][n]; k>=512 -> W1[k-512][n]
__global__ void pack_wcat(const float* __restrict__ Wgcn) {
    int idx = blockIdx.x * blockDim.x + threadIdx.x;
    if (idx >= 512 * 1024) return;
    int n = idx / 1024, k = idx % 1024;
    float v;
    if (k < 512) v = Wgcn[(size_t)k * 512 + n] - Wgcn[262144 + (size_t)k * 512 + n];
    else         v = Wgcn[262144 + (size_t)(k - 512) * 512 + n];
    g_Wcat[idx] = __float2half_rn(v);
}

// ---------------- adjacency softmax ---------------------------------------------
__global__ void build_A(const int* __restrict__ rows, const int* __restrict__ cols,
                        const float* __restrict__ e, int nnz) {
    __shared__ float lg[NJ][NJ];
    int tid = threadIdx.x;
    if (tid < NJ * NJ) lg[tid / NJ][tid % NJ] = -9e15f;
    __syncthreads();
    if (tid < nnz) lg[rows[tid]][cols[tid]] = e[tid];
    __syncthreads();
    if (tid < NJ) {
        float m = -9e15f;
        #pragma unroll
        for (int k = 0; k < NJ; k++) m = fmaxf(m, lg[tid][k]);
        float ex[NJ]; float s = 0.f;
        #pragma unroll
        for (int k = 0; k < NJ; k++) { ex[k] = __expf(lg[tid][k] - m); s += ex[k]; }
        float inv = 1.0f / s;
        #pragma unroll
        for (int k = 0; k < NJ; k++) g_A[tid * NJ + k] = ex[k] * inv;
    }
}

// ---------------- attention: one block per (b,h), warp per query row ------------
__global__ __launch_bounds__(544) void attn_kernel(const __half* __restrict__ qkv,
                                                   __half* __restrict__ o) {
    int b = blockIdx.x;
    int h = blockIdx.y;
    __shared__ float qs[NJ][64];
    __shared__ float ks[NJ][65];
    __shared__ float vs[NJ][64];

    int tid = threadIdx.y * 32 + threadIdx.x;
    for (int i = tid; i < NJ * 32; i += 544) {
        int j = i >> 5, e2 = i & 31;
        const __half* base = qkv + ((size_t)(b * NJ + j)) * 1536;
        float2 q2 = __half22float2(*(const __half2*)(base + h * 64 + e2 * 2));
        float2 k2 = __half22float2(*(const __half2*)(base + 512 + h * 64 + e2 * 2));
        float2 v2 = __half22float2(*(const __half2*)(base + 1024 + h * 64 + e2 * 2));
        qs[j][e2 * 2] = q2.x; qs[j][e2 * 2 + 1] = q2.y;
        ks[j][e2 * 2] = k2.x; ks[j][e2 * 2 + 1] = k2.y;
        vs[j][e2 * 2] = v2.x; vs[j][e2 * 2 + 1] = v2.y;
    }
    __syncthreads();

    int j = threadIdx.y;
    int lane = threadIdx.x;
    float s = -1e30f;
    if (lane < NJ) {
        float acc = 0.f;
        #pragma unroll
        for (int e = 0; e < 64; e++) acc = fmaf(qs[j][e], ks[lane][e], acc);
        s = acc * 0.125f;
    }
    float m = s;
    #pragma unroll
    for (int off = 16; off; off >>= 1) m = fmaxf(m, __shfl_xor_sync(0xffffffffu, m, off));
    float p = (lane < NJ) ? __expf(s - m) : 0.f;
    float sum = p;
    #pragma unroll
    for (int off = 16; off; off >>= 1) sum += __shfl_xor_sync(0xffffffffu, sum, off);
    p *= (1.0f / sum);

    float o0 = 0.f, o1 = 0.f;
    #pragma unroll
    for (int k = 0; k < NJ; k++) {
        float pk = __shfl_sync(0xffffffffu, p, k);
        o0 = fmaf(pk, vs[k][lane], o0);
        o1 = fmaf(pk, vs[k][lane + 32], o1);
    }
    __half* orow = o + ((size_t)(b * NJ + j)) * 512 + h * 64;
    orow[lane] = __float2half_rn(o0);
    orow[lane + 32] = __float2half_rn(o1);
}

// ---------------- premix: u_j = [A_jj*x_j ; sum_k A_jk*x_k] ---------------------
__global__ __launch_bounds__(544) void premix(const __half* __restrict__ x,
                                              __half* __restrict__ u) {
    int b = blockIdx.x;
    __shared__ float xs[NJ][512];
    __shared__ float Arow[NJ][NJ];
    __shared__ float Ad[NJ];
    int tid = threadIdx.y * 32 + threadIdx.x;
    for (int i = tid; i < NJ * 256; i += 544) {
        int k = i >> 8, e2 = i & 255;
        float2 v = __half22float2(*(const __half2*)(x + ((size_t)(b * NJ + k)) * 512 + e2 * 2));
        xs[k][e2 * 2] = v.x; xs[k][e2 * 2 + 1] = v.y;
    }
    if (tid < NJ * NJ) {
        int j = tid / NJ, k = tid % NJ;
        float a = g_A[tid];
        Arow[j][k] = a;
        if (j == k) Ad[j] = a;
    }
    __syncthreads();

    int j = threadIdx.y, lane = threadIdx.x;
    __half* ur = u + ((size_t)(b * NJ + j)) * 1024;
    float adiag = Ad[j];
    #pragma unroll
    for (int t = 0; t < 16; t++) {
        int d = lane + (t << 5);
        float z = 0.f;
        #pragma unroll
        for (int k = 0; k < NJ; k++) z = fmaf(Arow[j][k], xs[k][d], z);
        ur[d]       = __float2half_rn(adiag * xs[j][d]);
        ur[512 + d] = __float2half_rn(z);
    }
}

// ---------------- host launcher --------------------------------------------------
extern "C" void kernel_launch(void* const* d_in, const int* in_sizes, int n_in,
                              void* d_out, int out_size) {
    const float* src   = (const float*)d_in[0];
    const float* Wq    = (const float*)d_in[1];
    const float* bq    = (const float*)d_in[2];
    const float* Wk    = (const float*)d_in[3];
    const float* bk    = (const float*)d_in[4];
    const float* Wv    = (const float*)d_in[5];
    const float* bv    = (const float*)d_in[6];
    const float* Wo    = (const float*)d_in[7];
    const float* bo    = (const float*)d_in[8];
    const float* ln1_g = (const float*)d_in[9];
    const float* ln1_b = (const float*)d_in[10];
    const float* Wgcn  = (const float*)d_in[11];
    const float* egcn  = (const float*)d_in[12];
    const float* bgcn  = (const float*)d_in[13];
    const float* ln2_g = (const float*)d_in[14];
    const float* ln2_b = (const float*)d_in[15];
    const int*   mrows = (const int*)d_in[16];
    const int*   mcols = (const int*)d_in[17];
    int nnz = in_sizes[16];
    float* out = (float*)d_out;

    __half *p_srch, *p_qkv, *p_o, *p_xh, *p_u, *p_Wqkv, *p_Wot, *p_Wcat;
    float *p_bqkv;
    cudaGetSymbolAddress((void**)&p_srch, g_src_h);
    cudaGetSymbolAddress((void**)&p_qkv,  g_qkv);
    cudaGetSymbolAddress((void**)&p_o,    g_o);
    cudaGetSymbolAddress((void**)&p_xh,   g_x_h);
    cudaGetSymbolAddress((void**)&p_u,    g_u);
    cudaGetSymbolAddress((void**)&p_Wqkv, g_Wqkv);
    cudaGetSymbolAddress((void**)&p_bqkv, g_bqkv);
    cudaGetSymbolAddress((void**)&p_Wot,  g_Wo_t);
    cudaGetSymbolAddress((void**)&p_Wcat, g_Wcat);

    cudaFuncSetAttribute(tc_gemm, cudaFuncAttributeMaxDynamicSharedMemorySize, GEMM_SMEM);
    cudaFuncSetAttribute(ln_gemm_t<8,  false, true >, cudaFuncAttributeMaxDynamicSharedMemorySize, LNG_SMEM);
    cudaFuncSetAttribute(ln_gemm_t<16, true,  false>, cudaFuncAttributeMaxDynamicSharedMemorySize, LNG_SMEM);

    // conversions, weight packing, adjacency softmax
    conv_src<<<(BJ * 256 + 255) / 256, 256>>>(src);
    pack_qkv_w<<<(512 * 1536 + 255) / 256, 256>>>(Wq, Wk, Wv, bq, bk, bv);
    pack_wo<<<(512 * 512 + 255) / 256, 256>>>(Wo);
    pack_wcat<<<(512 * 1024 + 255) / 256, 256>>>(Wgcn);
    build_A<<<1, 512>>>(mrows, mcols, egcn, nnz);

    // fused QKV GEMM: [BJ,512] @ [512,1536] -> half
    tc_gemm<<<dim3(1536 / 256, BJ / 128), 256, GEMM_SMEM>>>(p_srch, p_Wqkv, p_bqkv, p_qkv, 1536);

    // attention
    attn_kernel<<<dim3(NB, NH), dim3(32, NJ)>>>(p_qkv, p_o);

    // fused: x = LN1(src + o @ Wo + bo) -> half
    ln_gemm_t<8, false, true><<<BJ / 64, 256, LNG_SMEM>>>(p_o, p_Wot, bo, src, ln1_g, ln1_b, p_xh);

    // premix u = [A_jj x_j ; sum_k A_jk x_k]
    premix<<<NB, dim3(32, NJ)>>>(p_xh, p_u);

    // fused: out = LN2(x + u @ Wcat + b_gcn) -> fp32
    ln_gemm_t<16, true, false><<<BJ / 64, 256, LNG_SMEM>>>(p_u, p_Wcat, bgcn, p_xh, ln2_g, ln2_b, out);
}

// round 7
// speedup vs baseline: 4.1710x; 1.0264x over previous
#include <cuda_runtime.h>
#include <cuda_fp16.h>
#include <cstdint>
#include <cstddef>

// Problem constants
#define BJ   69632           // 4096*17 rows
#define NB   4096
#define NJ   17
#define ND   512
#define NH   8
#define NDK  64

// ---------------- device scratch ------------------------------------------------
__device__ __half g_src_h[(size_t)BJ * 512];   // src as half
__device__ __half g_qkv  [(size_t)BJ * 1536];  // fused Q|K|V (half)
__device__ __half g_o    [(size_t)BJ * 512];   // attention output (half)
__device__ __half g_x_h  [(size_t)BJ * 512];   // LN1 output (half)
__device__ __half g_u    [(size_t)BJ * 1024];  // premixed GCN input (half)
__device__ __half g_Wqkv[1536 * 512];          // transposed [N][K] half
__device__ float  g_bqkv[1536];
__device__ __half g_Wo_t[512 * 512];           // transposed [N][K] half
__device__ __half g_Wcat[512 * 1024];          // [N=512][K=1024]: [W0-W1 ; W1]^T half
__device__ float  g_A[NJ * NJ];

// ---------------- helpers -------------------------------------------------------
__device__ __forceinline__ uint32_t smem_u32(const void* p) {
    uint32_t a;
    asm("{ .reg .u64 t; cvta.to.shared.u64 t, %1; cvt.u32.u64 %0, t; }" : "=r"(a) : "l"(p));
    return a;
}
__device__ __forceinline__ void cp16(uint32_t saddr, const void* gptr) {
    asm volatile("cp.async.cg.shared.global [%0], [%1], 16;" :: "r"(saddr), "l"(gptr));
}
__device__ __forceinline__ void cp_commit() { asm volatile("cp.async.commit_group;" ::: "memory"); }
__device__ __forceinline__ void cp_wait1()  { asm volatile("cp.async.wait_group 1;" ::: "memory"); }
__device__ __forceinline__ void cp_wait0()  { asm volatile("cp.async.wait_group 0;" ::: "memory"); }

__device__ __forceinline__ void ldsm4(uint32_t* r, uint32_t addr) {
    asm volatile("ldmatrix.sync.aligned.m8n8.x4.shared.b16 {%0,%1,%2,%3}, [%4];"
        : "=r"(r[0]), "=r"(r[1]), "=r"(r[2]), "=r"(r[3]) : "r"(addr));
}
__device__ __forceinline__ void mma_f16(float* d, const uint32_t* a, const uint32_t* b) {
    asm volatile(
        "mma.sync.aligned.m16n8k16.row.col.f32.f16.f16.f32 "
        "{%0,%1,%2,%3}, {%4,%5,%6,%7}, {%8,%9}, {%0,%1,%2,%3};"
        : "+f"(d[0]), "+f"(d[1]), "+f"(d[2]), "+f"(d[3])
        : "r"(a[0]), "r"(a[1]), "r"(a[2]), "r"(a[3]), "r"(b[0]), "r"(b[1]));
}

// ================= fp16 mma.sync GEMM: C[M,N] = A[M,512] @ Bt[N,512]^T (+bias) ==
// Tile: BM=128, BN=128, BK=64 halves, 256 threads (8 warps 2x4), warp tile 64x32.
// 3 stages x 32KB = 96KB smem -> 2 CTAs/SM (16 warps resident).
#define STAGE_BYTES 32768     // A: 128*128B=16KB, B: 128*128B=16KB
#define GEMM_SMEM   (3 * STAGE_BYTES)

__global__ __launch_bounds__(256, 2) void tc_gemm(const __half* __restrict__ A,
                                                  const __half* __restrict__ Bt,
                                                  const float* __restrict__ bias,
                                                  __half* __restrict__ C, int N) {
    extern __shared__ char smem[];
    const uint32_t sb = smem_u32(smem);
    const int tid  = threadIdx.x;
    const int lane = tid & 31;
    const int wid  = tid >> 5;
    const int warp_m = (wid & 1) * 64;
    const int warp_n = (wid >> 1) * 32;
    const int l7 = lane & 7;
    const int a_row_base = warp_m + l7 + ((lane & 8) ? 8 : 0);
    const int a_cc_add = (lane & 16) ? 1 : 0;
    const int b_row_base = warp_n + l7 + ((lane & 16) ? 8 : 0);
    const int b_cc_add = (lane & 8) ? 1 : 0;

    const __half* Abase = A  + (size_t)blockIdx.y * 128 * 512;
    const __half* Bbase = Bt + (size_t)blockIdx.x * 128 * 512;

    auto issue = [&](int t) {
        const int buf = t % 3;
        const uint32_t sA = sb + buf * STAGE_BYTES;
        const uint32_t sB = sA + 16384;
        const __half* Ab = Abase + t * 64;
        const __half* Bb = Bbase + t * 64;
        #pragma unroll
        for (int ll = 0; ll < 4; ++ll) {
            int id = tid + ll * 256, row = id >> 3, cc = id & 7;
            cp16(sA + row * 128 + ((cc ^ (row & 7)) << 4), Ab + (size_t)row * 512 + cc * 8);
        }
        #pragma unroll
        for (int ll = 0; ll < 4; ++ll) {
            int id = tid + ll * 256, row = id >> 3, cc = id & 7;
            cp16(sB + row * 128 + ((cc ^ (row & 7)) << 4), Bb + (size_t)row * 512 + cc * 8);
        }
        cp_commit();
    };

    float acc[4][4][4];
    #pragma unroll
    for (int i = 0; i < 4; ++i)
        #pragma unroll
        for (int j = 0; j < 4; ++j)
            #pragma unroll
            for (int q = 0; q < 4; ++q) acc[i][j][q] = 0.f;

    issue(0);
    issue(1);

    #pragma unroll 1
    for (int t = 0; t < 8; ++t) {
        if (t < 7) cp_wait1(); else cp_wait0();
        __syncthreads();
        if (t + 2 < 8) issue(t + 2);

        const int buf = t % 3;
        const uint32_t sA = sb + buf * STAGE_BYTES;
        const uint32_t sB = sA + 16384;

        #pragma unroll
        for (int q = 0; q < 4; ++q) {
            const int kc = 2 * q;
            uint32_t af[4][4], bf[2][4];
            #pragma unroll
            for (int i = 0; i < 4; ++i)
                ldsm4(af[i], sA + (uint32_t)(a_row_base + i * 16) * 128 +
                              (uint32_t)(((kc + a_cc_add) ^ l7) << 4));
            #pragma unroll
            for (int j2 = 0; j2 < 2; ++j2)
                ldsm4(bf[j2], sB + (uint32_t)(b_row_base + j2 * 16) * 128 +
                               (uint32_t)(((kc + b_cc_add) ^ l7) << 4));
            #pragma unroll
            for (int i = 0; i < 4; ++i)
                #pragma unroll
                for (int j = 0; j < 4; ++j)
                    mma_f16(acc[i][j], af[i], &bf[j >> 1][(j & 1) * 2]);
        }
    }

    // epilogue (registers only)
    const size_t rowBase = (size_t)blockIdx.y * 128 + warp_m + (lane >> 2);
    const int colBase = blockIdx.x * 128 + warp_n + (lane & 3) * 2;
    #pragma unroll
    for (int i = 0; i < 4; ++i) {
        #pragma unroll
        for (int j = 0; j < 4; ++j) {
            size_t m0 = rowBase + i * 16;
            int n0 = colBase + j * 8;
            float b0 = bias[n0], b1 = bias[n0 + 1];
            *(__half2*)(C + m0 * (size_t)N + n0) =
                __floats2half2_rn(acc[i][j][0] + b0, acc[i][j][1] + b1);
            *(__half2*)(C + (m0 + 8) * (size_t)N + n0) =
                __floats2half2_rn(acc[i][j][2] + b0, acc[i][j][3] + b1);
        }
    }
}

// ===== fused GEMM + bias + residual + LayerNorm (full 512-wide rows) ============
// BM=64, BN=512, BK=64, 256 threads (8 warps, each 64 rows x 64 cols).
#define LNG_STAGE (8192 + 65536)      // A: 64*128B, B: 512*128B
#define LNG_SMEM  (3 * LNG_STAGE)

template<int NCHUNK, bool RES_HALF, bool OUT_HALF>
__global__ __launch_bounds__(256) void ln_gemm_t(const __half* __restrict__ A,
                                                 const __half* __restrict__ Bt,
                                                 const float* __restrict__ bias,
                                                 const void* __restrict__ resid,
                                                 const float* __restrict__ gam,
                                                 const float* __restrict__ bet,
                                                 void* __restrict__ outp) {
    constexpr int K = NCHUNK * 64;
    extern __shared__ char smem[];
    const uint32_t sb = smem_u32(smem);
    const int tid  = threadIdx.x;
    const int lane = tid & 31;
    const int wid  = tid >> 5;
    const int warp_n = wid * 64;
    const int l7 = lane & 7;
    const int a_row_base = l7 + ((lane & 8) ? 8 : 0);
    const int a_cc_add = (lane & 16) ? 1 : 0;
    const int b_row_base = warp_n + l7 + ((lane & 16) ? 8 : 0);
    const int b_cc_add = (lane & 8) ? 1 : 0;

    const size_t rowBlk = (size_t)blockIdx.x * 64;
    const __half* Abase = A + rowBlk * K;

    auto issue = [&](int t) {
        const int buf = t % 3;
        const uint32_t sA = sb + buf * LNG_STAGE;
        const uint32_t sB = sA + 8192;
        const __half* Ab = Abase + t * 64;
        const __half* Bb = Bt + t * 64;
        #pragma unroll
        for (int ll = 0; ll < 2; ++ll) {
            int id = tid + ll * 256, row = id >> 3, cc = id & 7;
            cp16(sA + row * 128 + ((cc ^ (row & 7)) << 4), Ab + (size_t)row * K + cc * 8);
        }
        #pragma unroll
        for (int ll = 0; ll < 16; ++ll) {
            int id = tid + ll * 256, row = id >> 3, cc = id & 7;
            cp16(sB + row * 128 + ((cc ^ (row & 7)) << 4), Bb + (size_t)row * K + cc * 8);
        }
        cp_commit();
    };

    float acc[4][8][4];
    #pragma unroll
    for (int i = 0; i < 4; ++i)
        #pragma unroll
        for (int j = 0; j < 8; ++j)
            #pragma unroll
            for (int q = 0; q < 4; ++q) acc[i][j][q] = 0.f;

    issue(0);
    issue(1);

    #pragma unroll 1
    for (int t = 0; t < NCHUNK; ++t) {
        if (t < NCHUNK - 1) cp_wait1(); else cp_wait0();
        __syncthreads();
        if (t + 2 < NCHUNK) issue(t + 2);

        const int buf = t % 3;
        const uint32_t sA = sb + buf * LNG_STAGE;
        const uint32_t sB = sA + 8192;

        #pragma unroll
        for (int q = 0; q < 4; ++q) {
            const int kc = 2 * q;
            uint32_t af[4][4], bf[4][4];
            #pragma unroll
            for (int i = 0; i < 4; ++i)
                ldsm4(af[i], sA + (uint32_t)(a_row_base + i * 16) * 128 +
                              (uint32_t)(((kc + a_cc_add) ^ l7) << 4));
            #pragma unroll
            for (int j2 = 0; j2 < 4; ++j2)
                ldsm4(bf[j2], sB + (uint32_t)(b_row_base + j2 * 16) * 128 +
                               (uint32_t)(((kc + b_cc_add) ^ l7) << 4));
            #pragma unroll
            for (int i = 0; i < 4; ++i)
                #pragma unroll
                for (int j = 0; j < 8; ++j)
                    mma_f16(acc[i][j], af[i], &bf[j >> 1][(j & 1) * 2]);
        }
    }
    __syncthreads();   // protect smem reuse below

    // ---- epilogue: v = acc + bias + resid; LN over full row (512 cols) ----
    float2* red  = (float2*)smem;          // [64 rows][8 warps]
    float2* stat = (float2*)(smem + 4096); // [64 rows] (mean, inv)
    const int rq = lane >> 2;
    const int cq = (lane & 3) * 2;

    #pragma unroll
    for (int i = 0; i < 4; ++i) {
        #pragma unroll
        for (int h2 = 0; h2 < 2; ++h2) {
            int row_local = rq + i * 16 + h2 * 8;
            size_t grow = (rowBlk + row_local) * 512;
            float s = 0.f, ss = 0.f;
            #pragma unroll
            for (int j = 0; j < 8; ++j) {
                int col = warp_n + cq + j * 8;
                float2 sv;
                if (RES_HALF)
                    sv = __half22float2(*(const __half2*)((const __half*)resid + grow + col));
                else
                    sv = *(const float2*)((const float*)resid + grow + col);
                float v0 = acc[i][j][h2 * 2 + 0] + bias[col]     + sv.x;
                float v1 = acc[i][j][h2 * 2 + 1] + bias[col + 1] + sv.y;
                acc[i][j][h2 * 2 + 0] = v0;
                acc[i][j][h2 * 2 + 1] = v1;
                s += v0 + v1;
                ss = fmaf(v0, v0, ss); ss = fmaf(v1, v1, ss);
            }
            s  += __shfl_xor_sync(0xffffffffu, s, 1);  s  += __shfl_xor_sync(0xffffffffu, s, 2);
            ss += __shfl_xor_sync(0xffffffffu, ss, 1); ss += __shfl_xor_sync(0xffffffffu, ss, 2);
            if ((lane & 3) == 0) red[row_local * 8 + wid] = make_float2(s, ss);
        }
    }
    __syncthreads();
    if (tid < 64) {
        float s = 0.f, ss = 0.f;
        #pragma unroll
        for (int w = 0; w < 8; ++w) {
            float2 v = red[tid * 8 + w];
            s += v.x; ss += v.y;
        }
        float mean = s * (1.0f / 512.0f);
        float var  = ss * (1.0f / 512.0f) - mean * mean;
        stat[tid] = make_float2(mean, rsqrtf(var + 1e-5f));
    }
    __syncthreads();
    #pragma unroll
    for (int i = 0; i < 4; ++i) {
        #pragma unroll
        for (int h2 = 0; h2 < 2; ++h2) {
            int row_local = rq + i * 16 + h2 * 8;
            float2 st = stat[row_local];
            size_t grow = (rowBlk + row_local) * 512;
            #pragma unroll
            for (int j = 0; j < 8; ++j) {
                int col = warp_n + cq + j * 8;
                float y0 = (acc[i][j][h2 * 2 + 0] - st.x) * st.y * gam[col]     + bet[col];
                float y1 = (acc[i][j][h2 * 2 + 1] - st.x) * st.y * gam[col + 1] + bet[col + 1];
                if (OUT_HALF)
                    *(__half2*)((__half*)outp + grow + col) = __floats2half2_rn(y0, y1);
                else
                    *(float2*)((float*)outp + grow + col) = make_float2(y0, y1);
            }
        }
    }
}

// ---------------- src -> half ---------------------------------------------------
__global__ void conv_src(const float* __restrict__ src) {
    size_t idx = (size_t)blockIdx.x * blockDim.x + threadIdx.x;
    if (idx >= (size_t)BJ * 256) return;
    float2 v = *(const float2*)(src + idx * 2);
    *(__half2*)(g_src_h + idx * 2) = __floats2half2_rn(v.x, v.y);
}

// ---------------- weight packing (transpose to [N][K], half) --------------------
__global__ void pack_qkv_w(const float* __restrict__ Wq, const float* __restrict__ Wk,
                           const float* __restrict__ Wv, const float* __restrict__ bq,
                           const float* __restrict__ bk, const float* __restrict__ bv) {
    int idx = blockIdx.x * blockDim.x + threadIdx.x;
    if (idx >= 512 * 1536) return;
    int d = idx / 1536, cc2 = idx % 1536;
    int sel = cc2 / 512, cc = cc2 % 512;
    int h = cc / 64, e = cc % 64;
    const float* W = (sel == 0) ? Wq : (sel == 1) ? Wk : Wv;   // [H, D, DK]
    g_Wqkv[(size_t)cc2 * 512 + d] = __float2half_rn(W[((size_t)h * 512 + d) * 64 + e]);
    if (d == 0) {
        const float* bb = (sel == 0) ? bq : (sel == 1) ? bk : bv;
        g_bqkv[cc2] = bb[cc];
    }
}

__global__ void pack_wo(const float* __restrict__ Wo) {  // [512,512] -> [N][K]
    int idx = blockIdx.x * blockDim.x + threadIdx.x;
    if (idx >= 512 * 512) return;
    int n = idx / 512, k = idx % 512;
    g_Wo_t[idx] = __float2half_rn(Wo[(size_t)k * 512 + n]);
}

// W_cat[n][k]: k<512 -> (W0-W1)[k][n]; k>=512 -> W1[k-512][n]
__global__ void pack_wcat(const float* __restrict__ Wgcn) {
    int idx = blockIdx.x * blockDim.x + threadIdx.x;
    if (idx >= 512 * 1024) return;
    int n = idx / 1024, k = idx % 1024;
    float v;
    if (k < 512) v = Wgcn[(size_t)k * 512 + n] - Wgcn[262144 + (size_t)k * 512 + n];
    else         v = Wgcn[262144 + (size_t)(k - 512) * 512 + n];
    g_Wcat[idx] = __float2half_rn(v);
}

// ---------------- adjacency softmax ---------------------------------------------
__global__ void build_A(const int* __restrict__ rows, const int* __restrict__ cols,
                        const float* __restrict__ e, int nnz) {
    __shared__ float lg[NJ][NJ];
    int tid = threadIdx.x;
    if (tid < NJ * NJ) lg[tid / NJ][tid % NJ] = -9e15f;
    __syncthreads();
    if (tid < nnz) lg[rows[tid]][cols[tid]] = e[tid];
    __syncthreads();
    if (tid < NJ) {
        float m = -9e15f;
        #pragma unroll
        for (int k = 0; k < NJ; k++) m = fmaxf(m, lg[tid][k]);
        float ex[NJ]; float s = 0.f;
        #pragma unroll
        for (int k = 0; k < NJ; k++) { ex[k] = __expf(lg[tid][k] - m); s += ex[k]; }
        float inv = 1.0f / s;
        #pragma unroll
        for (int k = 0; k < NJ; k++) g_A[tid * NJ + k] = ex[k] * inv;
    }
}

// ---------------- attention: one block per (b,h), warp per query row ------------
__global__ __launch_bounds__(544) void attn_kernel(const __half* __restrict__ qkv,
                                                   __half* __restrict__ o) {
    int b = blockIdx.x;
    int h = blockIdx.y;
    __shared__ float qs[NJ][64];
    __shared__ float ks[NJ][65];
    __shared__ float vs[NJ][64];

    int tid = threadIdx.y * 32 + threadIdx.x;
    for (int i = tid; i < NJ * 32; i += 544) {
        int j = i >> 5, e2 = i & 31;
        const __half* base = qkv + ((size_t)(b * NJ + j)) * 1536;
        float2 q2 = __half22float2(*(const __half2*)(base + h * 64 + e2 * 2));
        float2 k2 = __half22float2(*(const __half2*)(base + 512 + h * 64 + e2 * 2));
        float2 v2 = __half22float2(*(const __half2*)(base + 1024 + h * 64 + e2 * 2));
        qs[j][e2 * 2] = q2.x; qs[j][e2 * 2 + 1] = q2.y;
        ks[j][e2 * 2] = k2.x; ks[j][e2 * 2 + 1] = k2.y;
        vs[j][e2 * 2] = v2.x; vs[j][e2 * 2 + 1] = v2.y;
    }
    __syncthreads();

    int j = threadIdx.y;
    int lane = threadIdx.x;
    float s = -1e30f;
    if (lane < NJ) {
        float acc = 0.f;
        #pragma unroll
        for (int e = 0; e < 64; e++) acc = fmaf(qs[j][e], ks[lane][e], acc);
        s = acc * 0.125f;
    }
    float m = s;
    #pragma unroll
    for (int off = 16; off; off >>= 1) m = fmaxf(m, __shfl_xor_sync(0xffffffffu, m, off));
    float p = (lane < NJ) ? __expf(s - m) : 0.f;
    float sum = p;
    #pragma unroll
    for (int off = 16; off; off >>= 1) sum += __shfl_xor_sync(0xffffffffu, sum, off);
    p *= (1.0f / sum);

    float o0 = 0.f, o1 = 0.f;
    #pragma unroll
    for (int k = 0; k < NJ; k++) {
        float pk = __shfl_sync(0xffffffffu, p, k);
        o0 = fmaf(pk, vs[k][lane], o0);
        o1 = fmaf(pk, vs[k][lane + 32], o1);
    }
    __half* orow = o + ((size_t)(b * NJ + j)) * 512 + h * 64;
    orow[lane] = __float2half_rn(o0);
    orow[lane + 32] = __float2half_rn(o1);
}

// ---------------- premix: u_j = [A_jj*x_j ; sum_k A_jk*x_k] ---------------------
__global__ __launch_bounds__(544) void premix(const __half* __restrict__ x,
                                              __half* __restrict__ u) {
    int b = blockIdx.x;
    __shared__ float xs[NJ][512];
    __shared__ float Arow[NJ][NJ];
    __shared__ float Ad[NJ];
    int tid = threadIdx.y * 32 + threadIdx.x;
    for (int i = tid; i < NJ * 256; i += 544) {
        int k = i >> 8, e2 = i & 255;
        float2 v = __half22float2(*(const __half2*)(x + ((size_t)(b * NJ + k)) * 512 + e2 * 2));
        xs[k][e2 * 2] = v.x; xs[k][e2 * 2 + 1] = v.y;
    }
    if (tid < NJ * NJ) {
        int j = tid / NJ, k = tid % NJ;
        float a = g_A[tid];
        Arow[j][k] = a;
        if (j == k) Ad[j] = a;
    }
    __syncthreads();

    int j = threadIdx.y, lane = threadIdx.x;
    __half* ur = u + ((size_t)(b * NJ + j)) * 1024;
    float adiag = Ad[j];
    #pragma unroll
    for (int t = 0; t < 16; t++) {
        int d = lane + (t << 5);
        float z = 0.f;
        #pragma unroll
        for (int k = 0; k < NJ; k++) z = fmaf(Arow[j][k], xs[k][d], z);
        ur[d]       = __float2half_rn(adiag * xs[j][d]);
        ur[512 + d] = __float2half_rn(z);
    }
}

// ---------------- host launcher --------------------------------------------------
extern "C" void kernel_launch(void* const* d_in, const int* in_sizes, int n_in,
                              void* d_out, int out_size) {
    const float* src   = (const float*)d_in[0];
    const float* Wq    = (const float*)d_in[1];
    const float* bq    = (const float*)d_in[2];
    const float* Wk    = (const float*)d_in[3];
    const float* bk    = (const float*)d_in[4];
    const float* Wv    = (const float*)d_in[5];
    const float* bv    = (const float*)d_in[6];
    const float* Wo    = (const float*)d_in[7];
    const float* bo    = (const float*)d_in[8];
    const float* ln1_g = (const float*)d_in[9];
    const float* ln1_b = (const float*)d_in[10];
    const float* Wgcn  = (const float*)d_in[11];
    const float* egcn  = (const float*)d_in[12];
    const float* bgcn  = (const float*)d_in[13];
    const float* ln2_g = (const float*)d_in[14];
    const float* ln2_b = (const float*)d_in[15];
    const int*   mrows = (const int*)d_in[16];
    const int*   mcols = (const int*)d_in[17];
    int nnz = in_sizes[16];
    float* out = (float*)d_out;

    __half *p_srch, *p_qkv, *p_o, *p_xh, *p_u, *p_Wqkv, *p_Wot, *p_Wcat;
    float *p_bqkv;
    cudaGetSymbolAddress((void**)&p_srch, g_src_h);
    cudaGetSymbolAddress((void**)&p_qkv,  g_qkv);
    cudaGetSymbolAddress((void**)&p_o,    g_o);
    cudaGetSymbolAddress((void**)&p_xh,   g_x_h);
    cudaGetSymbolAddress((void**)&p_u,    g_u);
    cudaGetSymbolAddress((void**)&p_Wqkv, g_Wqkv);
    cudaGetSymbolAddress((void**)&p_bqkv, g_bqkv);
    cudaGetSymbolAddress((void**)&p_Wot,  g_Wo_t);
    cudaGetSymbolAddress((void**)&p_Wcat, g_Wcat);

    cudaFuncSetAttribute(tc_gemm, cudaFuncAttributeMaxDynamicSharedMemorySize, GEMM_SMEM);
    cudaFuncSetAttribute(ln_gemm_t<8,  false, true >, cudaFuncAttributeMaxDynamicSharedMemorySize, LNG_SMEM);
    cudaFuncSetAttribute(ln_gemm_t<16, true,  false>, cudaFuncAttributeMaxDynamicSharedMemorySize, LNG_SMEM);

    // conversions, weight packing, adjacency softmax
    conv_src<<<(BJ * 256 + 255) / 256, 256>>>(src);
    pack_qkv_w<<<(512 * 1536 + 255) / 256, 256>>>(Wq, Wk, Wv, bq, bk, bv);
    pack_wo<<<(512 * 512 + 255) / 256, 256>>>(Wo);
    pack_wcat<<<(512 * 1024 + 255) / 256, 256>>>(Wgcn);
    build_A<<<1, 512>>>(mrows, mcols, egcn, nnz);

    // fused QKV GEMM: [BJ,512] @ [512,1536] -> half
    tc_gemm<<<dim3(1536 / 128, BJ / 128), 256, GEMM_SMEM>>>(p_srch, p_Wqkv, p_bqkv, p_qkv, 1536);

    // attention
    attn_kernel<<<dim3(NB, NH), dim3(32, NJ)>>>(p_qkv, p_o);

    // fused: x = LN1(src + o @ Wo + bo) -> half
    ln_gemm_t<8, false, true><<<BJ / 64, 256, LNG_SMEM>>>(p_o, p_Wot, bo, src, ln1_g, ln1_b, p_xh);

    // premix u = [A_jj x_j ; sum_k A_jk x_k]
    premix<<<NB, dim3(32, NJ)>>>(p_xh, p_u);

    // fused: out = LN2(x + u @ Wcat + b_gcn) -> fp32
    ln_gemm_t<16, true, false><<<BJ / 64, 256, LNG_SMEM>>>(p_u, p_Wcat, bgcn, p_xh, ln2_g, ln2_b, out);
}

// round 8
// speedup vs baseline: 4.2687x; 1.0234x over previous
#include <cuda_runtime.h>
#include <cuda_fp16.h>
#include <cstdint>
#include <cstddef>

// Problem constants
#define BJ   69632           // 4096*17 rows
#define NB   4096
#define NJ   17
#define ND   512
#define NH   8
#define NDK  64

// ---------------- device scratch ------------------------------------------------
__device__ __half g_src_h[(size_t)BJ * 512];   // src as half
__device__ __half g_qkv  [(size_t)BJ * 1536];  // fused Q|K|V (half)
__device__ __half g_o    [(size_t)BJ * 512];   // attention output (half)
__device__ __half g_x_h  [(size_t)BJ * 512];   // LN1 output (half)
__device__ __half g_u    [(size_t)BJ * 1024];  // premixed GCN input (half)
__device__ __half g_Wqkv[1536 * 512];          // transposed [N][K] half
__device__ float  g_bqkv[1536];
__device__ __half g_Wo_t[512 * 512];           // transposed [N][K] half
__device__ __half g_Wcat[512 * 1024];          // [N=512][K=1024]: [W0-W1 ; W1]^T half
__device__ float  g_A[NJ * NJ];

// ---------------- helpers -------------------------------------------------------
__device__ __forceinline__ uint32_t smem_u32(const void* p) {
    uint32_t a;
    asm("{ .reg .u64 t; cvta.to.shared.u64 t, %1; cvt.u32.u64 %0, t; }" : "=r"(a) : "l"(p));
    return a;
}
__device__ __forceinline__ void cp16(uint32_t saddr, const void* gptr) {
    asm volatile("cp.async.cg.shared.global [%0], [%1], 16;" :: "r"(saddr), "l"(gptr));
}
__device__ __forceinline__ void cp_commit() { asm volatile("cp.async.commit_group;" ::: "memory"); }
__device__ __forceinline__ void cp_wait1()  { asm volatile("cp.async.wait_group 1;" ::: "memory"); }
__device__ __forceinline__ void cp_wait0()  { asm volatile("cp.async.wait_group 0;" ::: "memory"); }

__device__ __forceinline__ void ldsm4(uint32_t* r, uint32_t addr) {
    asm volatile("ldmatrix.sync.aligned.m8n8.x4.shared.b16 {%0,%1,%2,%3}, [%4];"
        : "=r"(r[0]), "=r"(r[1]), "=r"(r[2]), "=r"(r[3]) : "r"(addr));
}
__device__ __forceinline__ void mma_f16(float* d, const uint32_t* a, const uint32_t* b) {
    asm volatile(
        "mma.sync.aligned.m16n8k16.row.col.f32.f16.f16.f32 "
        "{%0,%1,%2,%3}, {%4,%5,%6,%7}, {%8,%9}, {%0,%1,%2,%3};"
        : "+f"(d[0]), "+f"(d[1]), "+f"(d[2]), "+f"(d[3])
        : "r"(a[0]), "r"(a[1]), "r"(a[2]), "r"(a[3]), "r"(b[0]), "r"(b[1]));
}

// ================= fp16 mma.sync GEMM: C[M,N] = A[M,512] @ Bt[N,512]^T (+bias) ==
// Tile: BM=128, BN=128, BK=64 halves, 256 threads (8 warps 2x4), warp tile 64x32.
// 3 stages x 32KB = 96KB smem -> 2 CTAs/SM (16 warps resident).
#define STAGE_BYTES 32768     // A: 128*128B=16KB, B: 128*128B=16KB
#define GEMM_SMEM   (3 * STAGE_BYTES)

__global__ __launch_bounds__(256, 2) void tc_gemm(const __half* __restrict__ A,
                                                  const __half* __restrict__ Bt,
                                                  const float* __restrict__ bias,
                                                  __half* __restrict__ C, int N) {
    extern __shared__ char smem[];
    const uint32_t sb = smem_u32(smem);
    const int tid  = threadIdx.x;
    const int lane = tid & 31;
    const int wid  = tid >> 5;
    const int warp_m = (wid & 1) * 64;
    const int warp_n = (wid >> 1) * 32;
    const int l7 = lane & 7;
    const int a_row_base = warp_m + l7 + ((lane & 8) ? 8 : 0);
    const int a_cc_add = (lane & 16) ? 1 : 0;
    const int b_row_base = warp_n + l7 + ((lane & 16) ? 8 : 0);
    const int b_cc_add = (lane & 8) ? 1 : 0;

    const __half* Abase = A  + (size_t)blockIdx.y * 128 * 512;
    const __half* Bbase = Bt + (size_t)blockIdx.x * 128 * 512;

    auto issue = [&](int t) {
        const int buf = t % 3;
        const uint32_t sA = sb + buf * STAGE_BYTES;
        const uint32_t sB = sA + 16384;
        const __half* Ab = Abase + t * 64;
        const __half* Bb = Bbase + t * 64;
        #pragma unroll
        for (int ll = 0; ll < 4; ++ll) {
            int id = tid + ll * 256, row = id >> 3, cc = id & 7;
            cp16(sA + row * 128 + ((cc ^ (row & 7)) << 4), Ab + (size_t)row * 512 + cc * 8);
        }
        #pragma unroll
        for (int ll = 0; ll < 4; ++ll) {
            int id = tid + ll * 256, row = id >> 3, cc = id & 7;
            cp16(sB + row * 128 + ((cc ^ (row & 7)) << 4), Bb + (size_t)row * 512 + cc * 8);
        }
        cp_commit();
    };

    float acc[4][4][4];
    #pragma unroll
    for (int i = 0; i < 4; ++i)
        #pragma unroll
        for (int j = 0; j < 4; ++j)
            #pragma unroll
            for (int q = 0; q < 4; ++q) acc[i][j][q] = 0.f;

    issue(0);
    issue(1);

    #pragma unroll 1
    for (int t = 0; t < 8; ++t) {
        if (t < 7) cp_wait1(); else cp_wait0();
        __syncthreads();
        if (t + 2 < 8) issue(t + 2);

        const int buf = t % 3;
        const uint32_t sA = sb + buf * STAGE_BYTES;
        const uint32_t sB = sA + 16384;

        #pragma unroll
        for (int q = 0; q < 4; ++q) {
            const int kc = 2 * q;
            uint32_t af[4][4], bf[2][4];
            #pragma unroll
            for (int i = 0; i < 4; ++i)
                ldsm4(af[i], sA + (uint32_t)(a_row_base + i * 16) * 128 +
                              (uint32_t)(((kc + a_cc_add) ^ l7) << 4));
            #pragma unroll
            for (int j2 = 0; j2 < 2; ++j2)
                ldsm4(bf[j2], sB + (uint32_t)(b_row_base + j2 * 16) * 128 +
                               (uint32_t)(((kc + b_cc_add) ^ l7) << 4));
            #pragma unroll
            for (int i = 0; i < 4; ++i)
                #pragma unroll
                for (int j = 0; j < 4; ++j)
                    mma_f16(acc[i][j], af[i], &bf[j >> 1][(j & 1) * 2]);
        }
    }

    // epilogue (registers only)
    const size_t rowBase = (size_t)blockIdx.y * 128 + warp_m + (lane >> 2);
    const int colBase = blockIdx.x * 128 + warp_n + (lane & 3) * 2;
    #pragma unroll
    for (int i = 0; i < 4; ++i) {
        #pragma unroll
        for (int j = 0; j < 4; ++j) {
            size_t m0 = rowBase + i * 16;
            int n0 = colBase + j * 8;
            float b0 = bias[n0], b1 = bias[n0 + 1];
            *(__half2*)(C + m0 * (size_t)N + n0) =
                __floats2half2_rn(acc[i][j][0] + b0, acc[i][j][1] + b1);
            *(__half2*)(C + (m0 + 8) * (size_t)N + n0) =
                __floats2half2_rn(acc[i][j][2] + b0, acc[i][j][3] + b1);
        }
    }
}

// ===== fused GEMM + bias + residual + LayerNorm (full 512-wide rows) ============
// BM=64, BN=512, BK=64, 512 threads (16 warps 2x8), warp tile 32x64.
#define LNG_STAGE (8192 + 65536)      // A: 64*128B, B: 512*128B
#define LNG_SMEM  (3 * LNG_STAGE)

template<int NCHUNK, bool RES_HALF, bool OUT_HALF>
__global__ __launch_bounds__(512) void ln_gemm_t(const __half* __restrict__ A,
                                                 const __half* __restrict__ Bt,
                                                 const float* __restrict__ bias,
                                                 const void* __restrict__ resid,
                                                 const float* __restrict__ gam,
                                                 const float* __restrict__ bet,
                                                 void* __restrict__ outp) {
    constexpr int K = NCHUNK * 64;
    extern __shared__ char smem[];
    const uint32_t sb = smem_u32(smem);
    const int tid  = threadIdx.x;
    const int lane = tid & 31;
    const int wid  = tid >> 5;          // 0..15
    const int warp_m = (wid & 1) * 32;  // 2 warp-rows of 32
    const int wid_n  = wid >> 1;        // 0..7
    const int warp_n = wid_n * 64;      // 8 warp-cols of 64
    const int l7 = lane & 7;
    const int a_row_base = warp_m + l7 + ((lane & 8) ? 8 : 0);
    const int a_cc_add = (lane & 16) ? 1 : 0;
    const int b_row_base = warp_n + l7 + ((lane & 16) ? 8 : 0);
    const int b_cc_add = (lane & 8) ? 1 : 0;

    const size_t rowBlk = (size_t)blockIdx.x * 64;
    const __half* Abase = A + rowBlk * K;

    auto issue = [&](int t) {
        const int buf = t % 3;
        const uint32_t sA = sb + buf * LNG_STAGE;
        const uint32_t sB = sA + 8192;
        const __half* Ab = Abase + t * 64;
        const __half* Bb = Bt + t * 64;
        {
            int row = tid >> 3, cc = tid & 7;
            cp16(sA + row * 128 + ((cc ^ (row & 7)) << 4), Ab + (size_t)row * K + cc * 8);
        }
        #pragma unroll
        for (int ll = 0; ll < 8; ++ll) {
            int id = tid + ll * 512, row = id >> 3, cc = id & 7;
            cp16(sB + row * 128 + ((cc ^ (row & 7)) << 4), Bb + (size_t)row * K + cc * 8);
        }
        cp_commit();
    };

    float acc[2][8][4];
    #pragma unroll
    for (int i = 0; i < 2; ++i)
        #pragma unroll
        for (int j = 0; j < 8; ++j)
            #pragma unroll
            for (int q = 0; q < 4; ++q) acc[i][j][q] = 0.f;

    issue(0);
    issue(1);

    #pragma unroll 1
    for (int t = 0; t < NCHUNK; ++t) {
        if (t < NCHUNK - 1) cp_wait1(); else cp_wait0();
        __syncthreads();
        if (t + 2 < NCHUNK) issue(t + 2);

        const int buf = t % 3;
        const uint32_t sA = sb + buf * LNG_STAGE;
        const uint32_t sB = sA + 8192;

        #pragma unroll
        for (int q = 0; q < 4; ++q) {
            const int kc = 2 * q;
            uint32_t af[2][4], bf[4][4];
            #pragma unroll
            for (int i = 0; i < 2; ++i)
                ldsm4(af[i], sA + (uint32_t)(a_row_base + i * 16) * 128 +
                              (uint32_t)(((kc + a_cc_add) ^ l7) << 4));
            #pragma unroll
            for (int j2 = 0; j2 < 4; ++j2)
                ldsm4(bf[j2], sB + (uint32_t)(b_row_base + j2 * 16) * 128 +
                               (uint32_t)(((kc + b_cc_add) ^ l7) << 4));
            #pragma unroll
            for (int i = 0; i < 2; ++i)
                #pragma unroll
                for (int j = 0; j < 8; ++j)
                    mma_f16(acc[i][j], af[i], &bf[j >> 1][(j & 1) * 2]);
        }
    }
    __syncthreads();   // protect smem reuse below

    // ---- epilogue: v = acc + bias + resid; LN over full row (512 cols) ----
    float2* red  = (float2*)smem;          // [64 rows][8 warp-cols]
    float2* stat = (float2*)(smem + 4096); // [64 rows] (mean, inv)
    const int rq = lane >> 2;
    const int cq = (lane & 3) * 2;

    #pragma unroll
    for (int i = 0; i < 2; ++i) {
        #pragma unroll
        for (int h2 = 0; h2 < 2; ++h2) {
            int row_local = warp_m + i * 16 + h2 * 8 + rq;
            size_t grow = (rowBlk + row_local) * 512;
            float s = 0.f, ss = 0.f;
            #pragma unroll
            for (int j = 0; j < 8; ++j) {
                int col = warp_n + cq + j * 8;
                float2 sv;
                if (RES_HALF)
                    sv = __half22float2(*(const __half2*)((const __half*)resid + grow + col));
                else
                    sv = *(const float2*)((const float*)resid + grow + col);
                float v0 = acc[i][j][h2 * 2 + 0] + bias[col]     + sv.x;
                float v1 = acc[i][j][h2 * 2 + 1] + bias[col + 1] + sv.y;
                acc[i][j][h2 * 2 + 0] = v0;
                acc[i][j][h2 * 2 + 1] = v1;
                s += v0 + v1;
                ss = fmaf(v0, v0, ss); ss = fmaf(v1, v1, ss);
            }
            s  += __shfl_xor_sync(0xffffffffu, s, 1);  s  += __shfl_xor_sync(0xffffffffu, s, 2);
            ss += __shfl_xor_sync(0xffffffffu, ss, 1); ss += __shfl_xor_sync(0xffffffffu, ss, 2);
            if ((lane & 3) == 0) red[row_local * 8 + wid_n] = make_float2(s, ss);
        }
    }
    __syncthreads();
    if (tid < 64) {
        float s = 0.f, ss = 0.f;
        #pragma unroll
        for (int w = 0; w < 8; ++w) {
            float2 v = red[tid * 8 + w];
            s += v.x; ss += v.y;
        }
        float mean = s * (1.0f / 512.0f);
        float var  = ss * (1.0f / 512.0f) - mean * mean;
        stat[tid] = make_float2(mean, rsqrtf(var + 1e-5f));
    }
    __syncthreads();
    #pragma unroll
    for (int i = 0; i < 2; ++i) {
        #pragma unroll
        for (int h2 = 0; h2 < 2; ++h2) {
            int row_local = warp_m + i * 16 + h2 * 8 + rq;
            float2 st = stat[row_local];
            size_t grow = (rowBlk + row_local) * 512;
            #pragma unroll
            for (int j = 0; j < 8; ++j) {
                int col = warp_n + cq + j * 8;
                float y0 = (acc[i][j][h2 * 2 + 0] - st.x) * st.y * gam[col]     + bet[col];
                float y1 = (acc[i][j][h2 * 2 + 1] - st.x) * st.y * gam[col + 1] + bet[col + 1];
                if (OUT_HALF)
                    *(__half2*)((__half*)outp + grow + col) = __floats2half2_rn(y0, y1);
                else
                    *(float2*)((float*)outp + grow + col) = make_float2(y0, y1);
            }
        }
    }
}

// ---------------- src -> half ---------------------------------------------------
__global__ void conv_src(const float* __restrict__ src) {
    size_t idx = (size_t)blockIdx.x * blockDim.x + threadIdx.x;
    if (idx >= (size_t)BJ * 256) return;
    float2 v = *(const float2*)(src + idx * 2);
    *(__half2*)(g_src_h + idx * 2) = __floats2half2_rn(v.x, v.y);
}

// ---------------- weight packing (transpose to [N][K], half) --------------------
__global__ void pack_qkv_w(const float* __restrict__ Wq, const float* __restrict__ Wk,
                           const float* __restrict__ Wv, const float* __restrict__ bq,
                           const float* __restrict__ bk, const float* __restrict__ bv) {
    int idx = blockIdx.x * blockDim.x + threadIdx.x;
    if (idx >= 512 * 1536) return;
    int d = idx / 1536, cc2 = idx % 1536;
    int sel = cc2 / 512, cc = cc2 % 512;
    int h = cc / 64, e = cc % 64;
    const float* W = (sel == 0) ? Wq : (sel == 1) ? Wk : Wv;   // [H, D, DK]
    g_Wqkv[(size_t)cc2 * 512 + d] = __float2half_rn(W[((size_t)h * 512 + d) * 64 + e]);
    if (d == 0) {
        const float* bb = (sel == 0) ? bq : (sel == 1) ? bk : bv;
        g_bqkv[cc2] = bb[cc];
    }
}

__global__ void pack_wo(const float* __restrict__ Wo) {  // [512,512] -> [N][K]
    int idx = blockIdx.x * blockDim.x + threadIdx.x;
    if (idx >= 512 * 512) return;
    int n = idx / 512, k = idx % 512;
    g_Wo_t[idx] = __float2half_rn(Wo[(size_t)k * 512 + n]);
}

// W_cat[n][k]: k<512 -> (W0-W1)[k][n]; k>=512 -> W1[k-512][n]
__global__ void pack_wcat(const float* __restrict__ Wgcn) {
    int idx = blockIdx.x * blockDim.x + threadIdx.x;
    if (idx >= 512 * 1024) return;
    int n = idx / 1024, k = idx % 1024;
    float v;
    if (k < 512) v = Wgcn[(size_t)k * 512 + n] - Wgcn[262144 + (size_t)k * 512 + n];
    else         v = Wgcn[262144 + (size_t)(k - 512) * 512 + n];
    g_Wcat[idx] = __float2half_rn(v);
}

// ---------------- adjacency softmax ---------------------------------------------
__global__ void build_A(const int* __restrict__ rows, const int* __restrict__ cols,
                        const float* __restrict__ e, int nnz) {
    __shared__ float lg[NJ][NJ];
    int tid = threadIdx.x;
    if (tid < NJ * NJ) lg[tid / NJ][tid % NJ] = -9e15f;
    __syncthreads();
    if (tid < nnz) lg[rows[tid]][cols[tid]] = e[tid];
    __syncthreads();
    if (tid < NJ) {
        float m = -9e15f;
        #pragma unroll
        for (int k = 0; k < NJ; k++) m = fmaxf(m, lg[tid][k]);
        float ex[NJ]; float s = 0.f;
        #pragma unroll
        for (int k = 0; k < NJ; k++) { ex[k] = __expf(lg[tid][k] - m); s += ex[k]; }
        float inv = 1.0f / s;
        #pragma unroll
        for (int k = 0; k < NJ; k++) g_A[tid * NJ + k] = ex[k] * inv;
    }
}

// ---------------- attention: one block per batch b, all 8 heads ------------------
// Loads the full 17x1536 QKV slab coalesced into smem, then each warp j computes
// query j for every head. K buffer stride 516 floats -> conflict-free LDS.128.
#define KS_LD 516
#define ATTN_SMEM ((NJ * 512 + NJ * KS_LD + NJ * 512) * 4)

__global__ __launch_bounds__(544) void attn_kernel(const __half* __restrict__ qkv,
                                                   __half* __restrict__ o) {
    extern __shared__ float smf[];
    float* qs = smf;                 // [17][512]
    float* ks = qs + NJ * 512;       // [17][516]
    float* vs = ks + NJ * KS_LD;     // [17][512]

    int b = blockIdx.x;
    int tid = threadIdx.y * 32 + threadIdx.x;
    const __half* base = qkv + (size_t)b * NJ * 1536;

    for (int i = tid; i < NJ * 384; i += 544) {
        int row = i / 384, c4 = (i % 384) * 4;
        const __half2* p = (const __half2*)(base + (size_t)row * 1536 + c4);
        float2 v0 = __half22float2(p[0]);
        float2 v1 = __half22float2(p[1]);
        float4 val = make_float4(v0.x, v0.y, v1.x, v1.y);
        if (c4 < 512)       *(float4*)(qs + row * 512 + c4)          = val;
        else if (c4 < 1024) *(float4*)(ks + row * KS_LD + (c4 - 512)) = val;
        else                *(float4*)(vs + row * 512 + (c4 - 1024))  = val;
    }
    __syncthreads();

    int j = threadIdx.y;
    int lane = threadIdx.x;
    __half* orow = o + ((size_t)(b * NJ + j)) * 512;

    #pragma unroll 1
    for (int h = 0; h < NH; ++h) {
        const int hb = h * 64;
        float s = -1e30f;
        if (lane < NJ) {
            const float4* qp = (const float4*)(qs + j * 512 + hb);
            const float4* kp = (const float4*)(ks + lane * KS_LD + hb);
            float acc = 0.f;
            #pragma unroll
            for (int e4 = 0; e4 < 16; ++e4) {
                float4 qv = qp[e4], kv = kp[e4];
                acc = fmaf(qv.x, kv.x, fmaf(qv.y, kv.y, fmaf(qv.z, kv.z, fmaf(qv.w, kv.w, acc))));
            }
            s = acc * 0.125f;
        }
        float m = s;
        #pragma unroll
        for (int off = 16; off; off >>= 1) m = fmaxf(m, __shfl_xor_sync(0xffffffffu, m, off));
        float p = (lane < NJ) ? __expf(s - m) : 0.f;
        float sum = p;
        #pragma unroll
        for (int off = 16; off; off >>= 1) sum += __shfl_xor_sync(0xffffffffu, sum, off);
        p *= (1.0f / sum);

        float o0 = 0.f, o1 = 0.f;
        #pragma unroll
        for (int k = 0; k < NJ; ++k) {
            float pk = __shfl_sync(0xffffffffu, p, k);
            o0 = fmaf(pk, vs[k * 512 + hb + lane], o0);
            o1 = fmaf(pk, vs[k * 512 + hb + lane + 32], o1);
        }
        orow[hb + lane]      = __float2half_rn(o0);
        orow[hb + lane + 32] = __float2half_rn(o1);
    }
}

// ---------------- premix: u_j = [A_jj*x_j ; sum_k A_jk*x_k] ---------------------
__global__ __launch_bounds__(544) void premix(const __half* __restrict__ x,
                                              __half* __restrict__ u) {
    int b = blockIdx.x;
    __shared__ float xs[NJ][512];
    __shared__ float Arow[NJ][NJ];
    __shared__ float Ad[NJ];
    int tid = threadIdx.y * 32 + threadIdx.x;
    for (int i = tid; i < NJ * 256; i += 544) {
        int k = i >> 8, e2 = i & 255;
        float2 v = __half22float2(*(const __half2*)(x + ((size_t)(b * NJ + k)) * 512 + e2 * 2));
        xs[k][e2 * 2] = v.x; xs[k][e2 * 2 + 1] = v.y;
    }
    if (tid < NJ * NJ) {
        int j = tid / NJ, k = tid % NJ;
        float a = g_A[tid];
        Arow[j][k] = a;
        if (j == k) Ad[j] = a;
    }
    __syncthreads();

    int j = threadIdx.y, lane = threadIdx.x;
    __half* ur = u + ((size_t)(b * NJ + j)) * 1024;
    float adiag = Ad[j];
    #pragma unroll
    for (int t = 0; t < 16; t++) {
        int d = lane + (t << 5);
        float z = 0.f;
        #pragma unroll
        for (int k = 0; k < NJ; k++) z = fmaf(Arow[j][k], xs[k][d], z);
        ur[d]       = __float2half_rn(adiag * xs[j][d]);
        ur[512 + d] = __float2half_rn(z);
    }
}

// ---------------- host launcher --------------------------------------------------
extern "C" void kernel_launch(void* const* d_in, const int* in_sizes, int n_in,
                              void* d_out, int out_size) {
    const float* src   = (const float*)d_in[0];
    const float* Wq    = (const float*)d_in[1];
    const float* bq    = (const float*)d_in[2];
    const float* Wk    = (const float*)d_in[3];
    const float* bk    = (const float*)d_in[4];
    const float* Wv    = (const float*)d_in[5];
    const float* bv    = (const float*)d_in[6];
    const float* Wo    = (const float*)d_in[7];
    const float* bo    = (const float*)d_in[8];
    const float* ln1_g = (const float*)d_in[9];
    const float* ln1_b = (const float*)d_in[10];
    const float* Wgcn  = (const float*)d_in[11];
    const float* egcn  = (const float*)d_in[12];
    const float* bgcn  = (const float*)d_in[13];
    const float* ln2_g = (const float*)d_in[14];
    const float* ln2_b = (const float*)d_in[15];
    const int*   mrows = (const int*)d_in[16];
    const int*   mcols = (const int*)d_in[17];
    int nnz = in_sizes[16];
    float* out = (float*)d_out;

    __half *p_srch, *p_qkv, *p_o, *p_xh, *p_u, *p_Wqkv, *p_Wot, *p_Wcat;
    float *p_bqkv;
    cudaGetSymbolAddress((void**)&p_srch, g_src_h);
    cudaGetSymbolAddress((void**)&p_qkv,  g_qkv);
    cudaGetSymbolAddress((void**)&p_o,    g_o);
    cudaGetSymbolAddress((void**)&p_xh,   g_x_h);
    cudaGetSymbolAddress((void**)&p_u,    g_u);
    cudaGetSymbolAddress((void**)&p_Wqkv, g_Wqkv);
    cudaGetSymbolAddress((void**)&p_bqkv, g_bqkv);
    cudaGetSymbolAddress((void**)&p_Wot,  g_Wo_t);
    cudaGetSymbolAddress((void**)&p_Wcat, g_Wcat);

    cudaFuncSetAttribute(tc_gemm, cudaFuncAttributeMaxDynamicSharedMemorySize, GEMM_SMEM);
    cudaFuncSetAttribute(ln_gemm_t<8,  false, true >, cudaFuncAttributeMaxDynamicSharedMemorySize, LNG_SMEM);
    cudaFuncSetAttribute(ln_gemm_t<16, true,  false>, cudaFuncAttributeMaxDynamicSharedMemorySize, LNG_SMEM);
    cudaFuncSetAttribute(attn_kernel, cudaFuncAttributeMaxDynamicSharedMemorySize, ATTN_SMEM);

    // conversions, weight packing, adjacency softmax
    conv_src<<<(BJ * 256 + 255) / 256, 256>>>(src);
    pack_qkv_w<<<(512 * 1536 + 255) / 256, 256>>>(Wq, Wk, Wv, bq, bk, bv);
    pack_wo<<<(512 * 512 + 255) / 256, 256>>>(Wo);
    pack_wcat<<<(512 * 1024 + 255) / 256, 256>>>(Wgcn);
    build_A<<<1, 512>>>(mrows, mcols, egcn, nnz);

    // fused QKV GEMM: [BJ,512] @ [512,1536] -> half
    tc_gemm<<<dim3(1536 / 128, BJ / 128), 256, GEMM_SMEM>>>(p_srch, p_Wqkv, p_bqkv, p_qkv, 1536);

    // attention (per-batch blocks, all heads)
    attn_kernel<<<NB, dim3(32, NJ), ATTN_SMEM>>>(p_qkv, p_o);

    // fused: x = LN1(src + o @ Wo + bo) -> half
    ln_gemm_t<8, false, true><<<BJ / 64, 512, LNG_SMEM>>>(p_o, p_Wot, bo, src, ln1_g, ln1_b, p_xh);

    // premix u = [A_jj x_j ; sum_k A_jk x_k]
    premix<<<NB, dim3(32, NJ)>>>(p_xh, p_u);

    // fused: out = LN2(x + u @ Wcat + b_gcn) -> fp32
    ln_gemm_t<16, true, false><<<BJ / 64, 512, LNG_SMEM>>>(p_u, p_Wcat, bgcn, p_xh, ln2_g, ln2_b, out);
}

// round 9
// speedup vs baseline: 4.3401x; 1.0167x over previous
#include <cuda_runtime.h>
#include <cuda_fp16.h>
#include <cstdint>
#include <cstddef>

// Problem constants
#define BJ   69632           // 4096*17 rows
#define NB   4096
#define NJ   17
#define ND   512
#define NH   8
#define NDK  64

// ---------------- device scratch ------------------------------------------------
__device__ __half g_src_h[(size_t)BJ * 512];   // src as half
__device__ __half g_qkv  [(size_t)BJ * 1536];  // fused Q|K|V (half)
__device__ __half g_o    [(size_t)BJ * 512];   // attention output (half)
__device__ __half g_x_h  [(size_t)BJ * 512];   // LN1 output (half)
__device__ __half g_u    [(size_t)BJ * 1024];  // premixed GCN input (half)
__device__ __half g_Wqkv[1536 * 512];          // transposed [N][K] half
__device__ float  g_bqkv[1536];
__device__ __half g_Wo_t[512 * 512];           // transposed [N][K] half
__device__ __half g_Wcat[512 * 1024];          // [N=512][K=1024]: [W0-W1 ; W1]^T half
__device__ float  g_A[NJ * NJ];

// ---------------- helpers -------------------------------------------------------
__device__ __forceinline__ uint32_t smem_u32(const void* p) {
    uint32_t a;
    asm("{ .reg .u64 t; cvta.to.shared.u64 t, %1; cvt.u32.u64 %0, t; }" : "=r"(a) : "l"(p));
    return a;
}
__device__ __forceinline__ void cp16(uint32_t saddr, const void* gptr) {
    asm volatile("cp.async.cg.shared.global [%0], [%1], 16;" :: "r"(saddr), "l"(gptr));
}
__device__ __forceinline__ void cp_commit() { asm volatile("cp.async.commit_group;" ::: "memory"); }
__device__ __forceinline__ void cp_wait1()  { asm volatile("cp.async.wait_group 1;" ::: "memory"); }
__device__ __forceinline__ void cp_wait0()  { asm volatile("cp.async.wait_group 0;" ::: "memory"); }

__device__ __forceinline__ void ldsm4(uint32_t* r, uint32_t addr) {
    asm volatile("ldmatrix.sync.aligned.m8n8.x4.shared.b16 {%0,%1,%2,%3}, [%4];"
        : "=r"(r[0]), "=r"(r[1]), "=r"(r[2]), "=r"(r[3]) : "r"(addr));
}
__device__ __forceinline__ void mma_f16(float* d, const uint32_t* a, const uint32_t* b) {
    asm volatile(
        "mma.sync.aligned.m16n8k16.row.col.f32.f16.f16.f32 "
        "{%0,%1,%2,%3}, {%4,%5,%6,%7}, {%8,%9}, {%0,%1,%2,%3};"
        : "+f"(d[0]), "+f"(d[1]), "+f"(d[2]), "+f"(d[3])
        : "r"(a[0]), "r"(a[1]), "r"(a[2]), "r"(a[3]), "r"(b[0]), "r"(b[1]));
}

// ================= fp16 mma.sync GEMM: C[M,N] = A[M,512] @ Bt[N,512]^T (+bias) ==
// Tile: BM=128, BN=128, BK=64 halves, 256 threads (8 warps 2x4), warp tile 64x32.
// 3 stages x 32KB = 96KB smem -> 2 CTAs/SM (16 warps resident).
#define STAGE_BYTES 32768     // A: 128*128B=16KB, B: 128*128B=16KB
#define GEMM_SMEM   (3 * STAGE_BYTES)

__global__ __launch_bounds__(256, 2) void tc_gemm(const __half* __restrict__ A,
                                                  const __half* __restrict__ Bt,
                                                  const float* __restrict__ bias,
                                                  __half* __restrict__ C, int N) {
    extern __shared__ char smem[];
    const uint32_t sb = smem_u32(smem);
    const int tid  = threadIdx.x;
    const int lane = tid & 31;
    const int wid  = tid >> 5;
    const int warp_m = (wid & 1) * 64;
    const int warp_n = (wid >> 1) * 32;
    const int l7 = lane & 7;
    const int a_row_base = warp_m + l7 + ((lane & 8) ? 8 : 0);
    const int a_cc_add = (lane & 16) ? 1 : 0;
    const int b_row_base = warp_n + l7 + ((lane & 16) ? 8 : 0);
    const int b_cc_add = (lane & 8) ? 1 : 0;

    const __half* Abase = A  + (size_t)blockIdx.y * 128 * 512;
    const __half* Bbase = Bt + (size_t)blockIdx.x * 128 * 512;

    auto issue = [&](int t) {
        const int buf = t % 3;
        const uint32_t sA = sb + buf * STAGE_BYTES;
        const uint32_t sB = sA + 16384;
        const __half* Ab = Abase + t * 64;
        const __half* Bb = Bbase + t * 64;
        #pragma unroll
        for (int ll = 0; ll < 4; ++ll) {
            int id = tid + ll * 256, row = id >> 3, cc = id & 7;
            cp16(sA + row * 128 + ((cc ^ (row & 7)) << 4), Ab + (size_t)row * 512 + cc * 8);
        }
        #pragma unroll
        for (int ll = 0; ll < 4; ++ll) {
            int id = tid + ll * 256, row = id >> 3, cc = id & 7;
            cp16(sB + row * 128 + ((cc ^ (row & 7)) << 4), Bb + (size_t)row * 512 + cc * 8);
        }
        cp_commit();
    };

    float acc[4][4][4];
    #pragma unroll
    for (int i = 0; i < 4; ++i)
        #pragma unroll
        for (int j = 0; j < 4; ++j)
            #pragma unroll
            for (int q = 0; q < 4; ++q) acc[i][j][q] = 0.f;

    issue(0);
    issue(1);

    #pragma unroll 1
    for (int t = 0; t < 8; ++t) {
        if (t < 7) cp_wait1(); else cp_wait0();
        __syncthreads();
        if (t + 2 < 8) issue(t + 2);

        const int buf = t % 3;
        const uint32_t sA = sb + buf * STAGE_BYTES;
        const uint32_t sB = sA + 16384;

        #pragma unroll
        for (int q = 0; q < 4; ++q) {
            const int kc = 2 * q;
            uint32_t af[4][4], bf[2][4];
            #pragma unroll
            for (int i = 0; i < 4; ++i)
                ldsm4(af[i], sA + (uint32_t)(a_row_base + i * 16) * 128 +
                              (uint32_t)(((kc + a_cc_add) ^ l7) << 4));
            #pragma unroll
            for (int j2 = 0; j2 < 2; ++j2)
                ldsm4(bf[j2], sB + (uint32_t)(b_row_base + j2 * 16) * 128 +
                               (uint32_t)(((kc + b_cc_add) ^ l7) << 4));
            #pragma unroll
            for (int i = 0; i < 4; ++i)
                #pragma unroll
                for (int j = 0; j < 4; ++j)
                    mma_f16(acc[i][j], af[i], &bf[j >> 1][(j & 1) * 2]);
        }
    }

    // epilogue (registers only)
    const size_t rowBase = (size_t)blockIdx.y * 128 + warp_m + (lane >> 2);
    const int colBase = blockIdx.x * 128 + warp_n + (lane & 3) * 2;
    #pragma unroll
    for (int i = 0; i < 4; ++i) {
        #pragma unroll
        for (int j = 0; j < 4; ++j) {
            size_t m0 = rowBase + i * 16;
            int n0 = colBase + j * 8;
            float b0 = bias[n0], b1 = bias[n0 + 1];
            *(__half2*)(C + m0 * (size_t)N + n0) =
                __floats2half2_rn(acc[i][j][0] + b0, acc[i][j][1] + b1);
            *(__half2*)(C + (m0 + 8) * (size_t)N + n0) =
                __floats2half2_rn(acc[i][j][2] + b0, acc[i][j][3] + b1);
        }
    }
}

// ===== fused GEMM + bias + residual + LayerNorm (full 512-wide rows) ============
// BM=64, BN=512, BK=64, 512 threads (16 warps 2x8), warp tile 32x64.
#define LNG_STAGE (8192 + 65536)      // A: 64*128B, B: 512*128B
#define LNG_SMEM  (3 * LNG_STAGE)

template<int NCHUNK, bool RES_HALF, bool OUT_HALF>
__global__ __launch_bounds__(512) void ln_gemm_t(const __half* __restrict__ A,
                                                 const __half* __restrict__ Bt,
                                                 const float* __restrict__ bias,
                                                 const void* __restrict__ resid,
                                                 const float* __restrict__ gam,
                                                 const float* __restrict__ bet,
                                                 void* __restrict__ outp) {
    constexpr int K = NCHUNK * 64;
    extern __shared__ char smem[];
    const uint32_t sb = smem_u32(smem);
    const int tid  = threadIdx.x;
    const int lane = tid & 31;
    const int wid  = tid >> 5;          // 0..15
    const int warp_m = (wid & 1) * 32;  // 2 warp-rows of 32
    const int wid_n  = wid >> 1;        // 0..7
    const int warp_n = wid_n * 64;      // 8 warp-cols of 64
    const int l7 = lane & 7;
    const int a_row_base = warp_m + l7 + ((lane & 8) ? 8 : 0);
    const int a_cc_add = (lane & 16) ? 1 : 0;
    const int b_row_base = warp_n + l7 + ((lane & 16) ? 8 : 0);
    const int b_cc_add = (lane & 8) ? 1 : 0;

    const size_t rowBlk = (size_t)blockIdx.x * 64;
    const __half* Abase = A + rowBlk * K;

    auto issue = [&](int t) {
        const int buf = t % 3;
        const uint32_t sA = sb + buf * LNG_STAGE;
        const uint32_t sB = sA + 8192;
        const __half* Ab = Abase + t * 64;
        const __half* Bb = Bt + t * 64;
        {
            int row = tid >> 3, cc = tid & 7;
            cp16(sA + row * 128 + ((cc ^ (row & 7)) << 4), Ab + (size_t)row * K + cc * 8);
        }
        #pragma unroll
        for (int ll = 0; ll < 8; ++ll) {
            int id = tid + ll * 512, row = id >> 3, cc = id & 7;
            cp16(sB + row * 128 + ((cc ^ (row & 7)) << 4), Bb + (size_t)row * K + cc * 8);
        }
        cp_commit();
    };

    float acc[2][8][4];
    #pragma unroll
    for (int i = 0; i < 2; ++i)
        #pragma unroll
        for (int j = 0; j < 8; ++j)
            #pragma unroll
            for (int q = 0; q < 4; ++q) acc[i][j][q] = 0.f;

    issue(0);
    issue(1);

    #pragma unroll 1
    for (int t = 0; t < NCHUNK; ++t) {
        if (t < NCHUNK - 1) cp_wait1(); else cp_wait0();
        __syncthreads();
        if (t + 2 < NCHUNK) issue(t + 2);

        const int buf = t % 3;
        const uint32_t sA = sb + buf * LNG_STAGE;
        const uint32_t sB = sA + 8192;

        #pragma unroll
        for (int q = 0; q < 4; ++q) {
            const int kc = 2 * q;
            uint32_t af[2][4], bf[4][4];
            #pragma unroll
            for (int i = 0; i < 2; ++i)
                ldsm4(af[i], sA + (uint32_t)(a_row_base + i * 16) * 128 +
                              (uint32_t)(((kc + a_cc_add) ^ l7) << 4));
            #pragma unroll
            for (int j2 = 0; j2 < 4; ++j2)
                ldsm4(bf[j2], sB + (uint32_t)(b_row_base + j2 * 16) * 128 +
                               (uint32_t)(((kc + b_cc_add) ^ l7) << 4));
            #pragma unroll
            for (int i = 0; i < 2; ++i)
                #pragma unroll
                for (int j = 0; j < 8; ++j)
                    mma_f16(acc[i][j], af[i], &bf[j >> 1][(j & 1) * 2]);
        }
    }
    __syncthreads();   // protect smem reuse below

    // ---- epilogue: v = acc + bias + resid; LN over full row (512 cols) ----
    float2* red  = (float2*)smem;          // [64 rows][8 warp-cols]
    float2* stat = (float2*)(smem + 4096); // [64 rows] (mean, inv)
    const int rq = lane >> 2;
    const int cq = (lane & 3) * 2;

    #pragma unroll
    for (int i = 0; i < 2; ++i) {
        #pragma unroll
        for (int h2 = 0; h2 < 2; ++h2) {
            int row_local = warp_m + i * 16 + h2 * 8 + rq;
            size_t grow = (rowBlk + row_local) * 512;
            float s = 0.f, ss = 0.f;
            #pragma unroll
            for (int j = 0; j < 8; ++j) {
                int col = warp_n + cq + j * 8;
                float2 sv;
                if (RES_HALF)
                    sv = __half22float2(*(const __half2*)((const __half*)resid + grow + col));
                else
                    sv = *(const float2*)((const float*)resid + grow + col);
                float v0 = acc[i][j][h2 * 2 + 0] + bias[col]     + sv.x;
                float v1 = acc[i][j][h2 * 2 + 1] + bias[col + 1] + sv.y;
                acc[i][j][h2 * 2 + 0] = v0;
                acc[i][j][h2 * 2 + 1] = v1;
                s += v0 + v1;
                ss = fmaf(v0, v0, ss); ss = fmaf(v1, v1, ss);
            }
            s  += __shfl_xor_sync(0xffffffffu, s, 1);  s  += __shfl_xor_sync(0xffffffffu, s, 2);
            ss += __shfl_xor_sync(0xffffffffu, ss, 1); ss += __shfl_xor_sync(0xffffffffu, ss, 2);
            if ((lane & 3) == 0) red[row_local * 8 + wid_n] = make_float2(s, ss);
        }
    }
    __syncthreads();
    if (tid < 64) {
        float s = 0.f, ss = 0.f;
        #pragma unroll
        for (int w = 0; w < 8; ++w) {
            float2 v = red[tid * 8 + w];
            s += v.x; ss += v.y;
        }
        float mean = s * (1.0f / 512.0f);
        float var  = ss * (1.0f / 512.0f) - mean * mean;
        stat[tid] = make_float2(mean, rsqrtf(var + 1e-5f));
    }
    __syncthreads();
    #pragma unroll
    for (int i = 0; i < 2; ++i) {
        #pragma unroll
        for (int h2 = 0; h2 < 2; ++h2) {
            int row_local = warp_m + i * 16 + h2 * 8 + rq;
            float2 st = stat[row_local];
            size_t grow = (rowBlk + row_local) * 512;
            #pragma unroll
            for (int j = 0; j < 8; ++j) {
                int col = warp_n + cq + j * 8;
                float y0 = (acc[i][j][h2 * 2 + 0] - st.x) * st.y * gam[col]     + bet[col];
                float y1 = (acc[i][j][h2 * 2 + 1] - st.x) * st.y * gam[col + 1] + bet[col + 1];
                if (OUT_HALF)
                    *(__half2*)((__half*)outp + grow + col) = __floats2half2_rn(y0, y1);
                else
                    *(float2*)((float*)outp + grow + col) = make_float2(y0, y1);
            }
        }
    }
}

// ---------------- src -> half (float4 per thread) -------------------------------
__global__ void conv_src(const float* __restrict__ src) {
    size_t idx = (size_t)blockIdx.x * blockDim.x + threadIdx.x;
    if (idx >= (size_t)BJ * 128) return;
    float4 v = *(const float4*)(src + idx * 4);
    __half2 a = __floats2half2_rn(v.x, v.y);
    __half2 b = __floats2half2_rn(v.z, v.w);
    uint2 w;
    w.x = *(uint32_t*)&a;
    w.y = *(uint32_t*)&b;
    *(uint2*)(g_src_h + idx * 4) = w;
}

// ---------------- weight packing (transpose to [N][K], half) --------------------
__global__ void pack_qkv_w(const float* __restrict__ Wq, const float* __restrict__ Wk,
                           const float* __restrict__ Wv, const float* __restrict__ bq,
                           const float* __restrict__ bk, const float* __restrict__ bv) {
    int idx = blockIdx.x * blockDim.x + threadIdx.x;
    if (idx >= 512 * 1536) return;
    int d = idx / 1536, cc2 = idx % 1536;
    int sel = cc2 / 512, cc = cc2 % 512;
    int h = cc / 64, e = cc % 64;
    const float* W = (sel == 0) ? Wq : (sel == 1) ? Wk : Wv;   // [H, D, DK]
    g_Wqkv[(size_t)cc2 * 512 + d] = __float2half_rn(W[((size_t)h * 512 + d) * 64 + e]);
    if (d == 0) {
        const float* bb = (sel == 0) ? bq : (sel == 1) ? bk : bv;
        g_bqkv[cc2] = bb[cc];
    }
}

__global__ void pack_wo(const float* __restrict__ Wo) {  // [512,512] -> [N][K]
    int idx = blockIdx.x * blockDim.x + threadIdx.x;
    if (idx >= 512 * 512) return;
    int n = idx / 512, k = idx % 512;
    g_Wo_t[idx] = __float2half_rn(Wo[(size_t)k * 512 + n]);
}

// W_cat[n][k]: k<512 -> (W0-W1)[k][n]; k>=512 -> W1[k-512][n]
__global__ void pack_wcat(const float* __restrict__ Wgcn) {
    int idx = blockIdx.x * blockDim.x + threadIdx.x;
    if (idx >= 512 * 1024) return;
    int n = idx / 1024, k = idx % 1024;
    float v;
    if (k < 512) v = Wgcn[(size_t)k * 512 + n] - Wgcn[262144 + (size_t)k * 512 + n];
    else         v = Wgcn[262144 + (size_t)(k - 512) * 512 + n];
    g_Wcat[idx] = __float2half_rn(v);
}

// ---------------- adjacency softmax ---------------------------------------------
__global__ void build_A(const int* __restrict__ rows, const int* __restrict__ cols,
                        const float* __restrict__ e, int nnz) {
    __shared__ float lg[NJ][NJ];
    int tid = threadIdx.x;
    if (tid < NJ * NJ) lg[tid / NJ][tid % NJ] = -9e15f;
    __syncthreads();
    if (tid < nnz) lg[rows[tid]][cols[tid]] = e[tid];
    __syncthreads();
    if (tid < NJ) {
        float m = -9e15f;
        #pragma unroll
        for (int k = 0; k < NJ; k++) m = fmaxf(m, lg[tid][k]);
        float ex[NJ]; float s = 0.f;
        #pragma unroll
        for (int k = 0; k < NJ; k++) { ex[k] = __expf(lg[tid][k] - m); s += ex[k]; }
        float inv = 1.0f / s;
        #pragma unroll
        for (int k = 0; k < NJ; k++) g_A[tid * NJ + k] = ex[k] * inv;
    }
}

// ---------------- attention: one block per batch b, 9 warps, half2 smem ---------
// q/k/v stored as half2 words: q stride 257, k stride 259 (conflict-free lane
// dots: 259 mod 32 = 3, coprime), v stride 257. 52.6KB smem -> 4 blocks/SM.
#define QLD 257
#define KLD 259
#define VLD 257
#define ATTN_SMEM (NJ * (QLD + KLD + VLD) * 4)

__global__ __launch_bounds__(288) void attn_kernel(const __half* __restrict__ qkv,
                                                   __half* __restrict__ o) {
    extern __shared__ uint32_t sm2[];
    uint32_t* qs = sm2;
    uint32_t* ks = qs + NJ * QLD;
    uint32_t* vs = ks + NJ * KLD;

    int b = blockIdx.x;
    int tid = threadIdx.x;
    const uint32_t* base = (const uint32_t*)(qkv + (size_t)b * NJ * 1536);

    for (int i = tid; i < NJ * 768; i += 288) {
        int row = i / 768, c = i % 768;
        uint32_t w = base[row * 768 + c];
        if (c < 256)      qs[row * QLD + c]        = w;
        else if (c < 512) ks[row * KLD + (c - 256)] = w;
        else              vs[row * VLD + (c - 512)] = w;
    }
    __syncthreads();

    int wrp = tid >> 5, lane = tid & 31;
    #pragma unroll 1
    for (int rep = 0; rep < 2; ++rep) {
        int j = wrp + rep * 9;
        if (j >= NJ) break;
        __half* orow = o + ((size_t)(b * NJ + j)) * 512;

        #pragma unroll 1
        for (int h = 0; h < NH; ++h) {
            const int hw = h * 32;    // half2-word offset of this head
            float s = -1e30f;
            if (lane < NJ) {
                const uint32_t* qp = qs + j * QLD + hw;
                const uint32_t* kp = ks + lane * KLD + hw;
                float acc = 0.f;
                #pragma unroll
                for (int e = 0; e < 32; ++e) {
                    float2 qv = __half22float2(*(const __half2*)&qp[e]);
                    float2 kv = __half22float2(*(const __half2*)&kp[e]);
                    acc = fmaf(qv.x, kv.x, fmaf(qv.y, kv.y, acc));
                }
                s = acc * 0.125f;
            }
            float m = s;
            #pragma unroll
            for (int off = 16; off; off >>= 1) m = fmaxf(m, __shfl_xor_sync(0xffffffffu, m, off));
            float p = (lane < NJ) ? __expf(s - m) : 0.f;
            float sum = p;
            #pragma unroll
            for (int off = 16; off; off >>= 1) sum += __shfl_xor_sync(0xffffffffu, sum, off);
            p *= (1.0f / sum);

            const int wsel = lane & 1;
            const int widx = hw + (lane >> 1);
            float o0 = 0.f, o1 = 0.f;
            #pragma unroll
            for (int k = 0; k < NJ; ++k) {
                float pk = __shfl_sync(0xffffffffu, p, k);
                __half2 w0 = *(__half2*)&vs[k * VLD + widx];
                __half2 w1 = *(__half2*)&vs[k * VLD + widx + 16];
                float v0 = wsel ? __high2float(w0) : __low2float(w0);
                float v1 = wsel ? __high2float(w1) : __low2float(w1);
                o0 = fmaf(pk, v0, o0);
                o1 = fmaf(pk, v1, o1);
            }
            orow[h * 64 + lane]      = __float2half_rn(o0);
            orow[h * 64 + lane + 32] = __float2half_rn(o1);
        }
    }
}

// ---------------- premix: u_j = [A_jj*x_j ; sum_k A_jk*x_k] ---------------------
__global__ __launch_bounds__(544) void premix(const __half* __restrict__ x,
                                              __half* __restrict__ u) {
    int b = blockIdx.x;
    __shared__ float xs[NJ][512];
    __shared__ float Arow[NJ][NJ];
    __shared__ float Ad[NJ];
    int tid = threadIdx.y * 32 + threadIdx.x;
    for (int i = tid; i < NJ * 256; i += 544) {
        int k = i >> 8, e2 = i & 255;
        float2 v = __half22float2(*(const __half2*)(x + ((size_t)(b * NJ + k)) * 512 + e2 * 2));
        xs[k][e2 * 2] = v.x; xs[k][e2 * 2 + 1] = v.y;
    }
    if (tid < NJ * NJ) {
        int j = tid / NJ, k = tid % NJ;
        float a = g_A[tid];
        Arow[j][k] = a;
        if (j == k) Ad[j] = a;
    }
    __syncthreads();

    int j = threadIdx.y, lane = threadIdx.x;
    __half* ur = u + ((size_t)(b * NJ + j)) * 1024;
    float adiag = Ad[j];
    #pragma unroll
    for (int t = 0; t < 16; t++) {
        int d = lane + (t << 5);
        float z = 0.f;
        #pragma unroll
        for (int k = 0; k < NJ; k++) z = fmaf(Arow[j][k], xs[k][d], z);
        ur[d]       = __float2half_rn(adiag * xs[j][d]);
        ur[512 + d] = __float2half_rn(z);
    }
}

// ---------------- host launcher --------------------------------------------------
extern "C" void kernel_launch(void* const* d_in, const int* in_sizes, int n_in,
                              void* d_out, int out_size) {
    const float* src   = (const float*)d_in[0];
    const float* Wq    = (const float*)d_in[1];
    const float* bq    = (const float*)d_in[2];
    const float* Wk    = (const float*)d_in[3];
    const float* bk    = (const float*)d_in[4];
    const float* Wv    = (const float*)d_in[5];
    const float* bv    = (const float*)d_in[6];
    const float* Wo    = (const float*)d_in[7];
    const float* bo    = (const float*)d_in[8];
    const float* ln1_g = (const float*)d_in[9];
    const float* ln1_b = (const float*)d_in[10];
    const float* Wgcn  = (const float*)d_in[11];
    const float* egcn  = (const float*)d_in[12];
    const float* bgcn  = (const float*)d_in[13];
    const float* ln2_g = (const float*)d_in[14];
    const float* ln2_b = (const float*)d_in[15];
    const int*   mrows = (const int*)d_in[16];
    const int*   mcols = (const int*)d_in[17];
    int nnz = in_sizes[16];
    float* out = (float*)d_out;

    __half *p_srch, *p_qkv, *p_o, *p_xh, *p_u, *p_Wqkv, *p_Wot, *p_Wcat;
    float *p_bqkv;
    cudaGetSymbolAddress((void**)&p_srch, g_src_h);
    cudaGetSymbolAddress((void**)&p_qkv,  g_qkv);
    cudaGetSymbolAddress((void**)&p_o,    g_o);
    cudaGetSymbolAddress((void**)&p_xh,   g_x_h);
    cudaGetSymbolAddress((void**)&p_u,    g_u);
    cudaGetSymbolAddress((void**)&p_Wqkv, g_Wqkv);
    cudaGetSymbolAddress((void**)&p_bqkv, g_bqkv);
    cudaGetSymbolAddress((void**)&p_Wot,  g_Wo_t);
    cudaGetSymbolAddress((void**)&p_Wcat, g_Wcat);

    // One-time resource setup (outside graph capture: first call is the
    // correctness run; capture happens on a later call).
    static cudaStream_t s_side = nullptr;
    static cudaEvent_t e_fork = nullptr, e_join = nullptr;
    if (!s_side) {
        cudaStreamCreateWithFlags(&s_side, cudaStreamNonBlocking);
        cudaEventCreateWithFlags(&e_fork, cudaEventDisableTiming);
        cudaEventCreateWithFlags(&e_join, cudaEventDisableTiming);
        cudaFuncSetAttribute(tc_gemm, cudaFuncAttributeMaxDynamicSharedMemorySize, GEMM_SMEM);
        cudaFuncSetAttribute(ln_gemm_t<8,  false, true >, cudaFuncAttributeMaxDynamicSharedMemorySize, LNG_SMEM);
        cudaFuncSetAttribute(ln_gemm_t<16, true,  false>, cudaFuncAttributeMaxDynamicSharedMemorySize, LNG_SMEM);
        cudaFuncSetAttribute(attn_kernel, cudaFuncAttributeMaxDynamicSharedMemorySize, ATTN_SMEM);
    }

    // ---- fork: side branch packs weights not needed until ln_gemm1/premix/ln_gemm2
    cudaEventRecord(e_fork, 0);
    cudaStreamWaitEvent(s_side, e_fork, 0);
    pack_wo<<<(512 * 512 + 255) / 256, 256, 0, s_side>>>(Wo);
    pack_wcat<<<(512 * 1024 + 255) / 256, 256, 0, s_side>>>(Wgcn);
    build_A<<<1, 512, 0, s_side>>>(mrows, mcols, egcn, nnz);
    cudaEventRecord(e_join, s_side);

    // ---- main branch
    conv_src<<<(BJ * 128 + 255) / 256, 256>>>(src);
    pack_qkv_w<<<(512 * 1536 + 255) / 256, 256>>>(Wq, Wk, Wv, bq, bk, bv);

    // fused QKV GEMM: [BJ,512] @ [512,1536] -> half
    tc_gemm<<<dim3(1536 / 128, BJ / 128), 256, GEMM_SMEM>>>(p_srch, p_Wqkv, p_bqkv, p_qkv, 1536);

    // attention (per-batch blocks, all heads, 9 warps x 2 queries)
    attn_kernel<<<NB, 288, ATTN_SMEM>>>(p_qkv, p_o);

    // ---- join side branch before consumers of Wo_t / Wcat / A
    cudaStreamWaitEvent(0, e_join, 0);

    // fused: x = LN1(src + o @ Wo + bo) -> half
    ln_gemm_t<8, false, true><<<BJ / 64, 512, LNG_SMEM>>>(p_o, p_Wot, bo, src, ln1_g, ln1_b, p_xh);

    // premix u = [A_jj x_j ; sum_k A_jk x_k]
    premix<<<NB, dim3(32, NJ)>>>(p_xh, p_u);

    // fused: out = LN2(x + u @ Wcat + b_gcn) -> fp32
    ln_gemm_t<16, true, false><<<BJ / 64, 512, LNG_SMEM>>>(p_u, p_Wcat, bgcn, p_xh, ln2_g, ln2_b, out);
}